// round 10
// baseline (speedup 1.0000x reference)
#include <cuda_runtime.h>
#include <cooperative_groups.h>
namespace cg = cooperative_groups;

#define NN 100000
#define NE 1200000
#define D 64
#define NL 3
#define NM 5000
#define NO 24
#define BN_EPS 1e-5f
#define NB_SCAN ((NN + 1023) / 1024)
#define HS 68          // smem row stride (floats): 272B, float4-aligned, conflict-free
#define RPB 96         // rows per block tile (3 rows/thread, 5 blocks/SM)
#define COOP_BLOCKS 592
#define NSM 148
#define PGRID (5 * NSM)                    // persistent grid
#define SMEM_G ((RPB * HS + D * D) * 4)    // 42496 B dynamic

typedef unsigned long long ull;

// ---------------- scratch ----------------
__device__ __align__(128) float g_X0 [NN * D];
__device__ __align__(128) float g_T  [NN * D];
__device__ __align__(128) float g_XS [NL * NN * D];
__device__ __align__(128) float g_G  [NM * D];
__device__ __align__(128) float g_TG [NM * D];
__device__ __align__(128) float g_stats[4 * 2 * D];
__device__ __align__(128) int g_deg   [NN];
__device__ __align__(128) int g_cur   [NN];
__device__ __align__(128) int g_rowptr[NN + 1];
__device__ __align__(128) int g_csr   [NE];
__device__ __align__(128) int g_bsum  [NB_SCAN];
__device__ __align__(128) int g_boff  [NB_SCAN];
__device__ __align__(128) int g_molptr[NM + 1];

// ---------------- f32x2 helpers ----------------
__device__ __forceinline__ ull ffma2(ull a, ull b, ull c) {
    ull d; asm("fma.rn.f32x2 %0, %1, %2, %3;" : "=l"(d) : "l"(a), "l"(b), "l"(c));
    return d;
}
__device__ __forceinline__ ull pack2(float x) {
    ull r; asm("mov.b64 %0, {%1, %1};" : "=l"(r) : "f"(x)); return r;
}
__device__ __forceinline__ float2 u2f(ull v) {
    float2 f; asm("mov.b64 {%0, %1}, %2;" : "=f"(f.x), "=f"(f.y) : "l"(v)); return f;
}

// ---------------- init ----------------
__global__ void k_init() {
    int t = blockIdx.x * blockDim.x + threadIdx.x;
    if (t < NN) { g_deg[t] = 0; g_cur[t] = 0; }
    if (t < 4 * 2 * D) g_stats[t] = 0.f;
}

__global__ void k_embed(const int* __restrict__ atom_ids, const float* __restrict__ embW) {
    int t = blockIdx.x * blockDim.x + threadIdx.x;
    if (t >= NN * 16) return;
    int n = t >> 4, c = (t & 15) << 2;
    int a = __ldg(atom_ids + n);
    *(float4*)(g_X0 + (size_t)n * D + c) = *(const float4*)(embW + (size_t)a * D + c);
}

// ---------------- cooperative CSR build -----------------
__global__ void k_csr_coop(const int* __restrict__ src, const int* __restrict__ dst) {
    cg::grid_group grid = cg::this_grid();
    int tid = threadIdx.x, bid = blockIdx.x;
    int gt = bid * 256 + tid, gs = gridDim.x * 256;

    for (int e = gt; e < NE; e += gs) atomicAdd(&g_deg[__ldg(dst + e)], 1);
    grid.sync();

    __shared__ int sh[256];
    if (bid < NB_SCAN) {
        int base = bid * 1024;
        int loc[4]; int s = 0;
        #pragma unroll
        for (int j = 0; j < 4; j++) {
            int i = base + tid * 4 + j;
            int v = (i < NN) ? g_deg[i] : 0;
            s += v; loc[j] = s;
        }
        int excl_in = s;
        sh[tid] = excl_in; __syncthreads();
        for (int off = 1; off < 256; off <<= 1) {
            int t2 = (tid >= off) ? sh[tid - off] : 0;
            __syncthreads();
            sh[tid] += t2;
            __syncthreads();
        }
        int pre = sh[tid] - excl_in;
        #pragma unroll
        for (int j = 0; j < 4; j++) {
            int i = base + tid * 4 + j;
            if (i < NN) g_rowptr[i + 1] = pre + loc[j];
        }
        if (tid == 255) g_bsum[bid] = sh[255];
    }
    grid.sync();

    if (bid == 0 && tid < 32) {
        int carry = 0;
        for (int b = 0; b < NB_SCAN; b += 32) {
            int idx = b + tid;
            int v = (idx < NB_SCAN) ? g_bsum[idx] : 0;
            int x = v;
            #pragma unroll
            for (int off = 1; off < 32; off <<= 1) {
                int y = __shfl_up_sync(0xffffffff, x, off);
                if (tid >= off) x += y;
            }
            if (idx < NB_SCAN) g_boff[idx] = carry + x - v;
            carry += __shfl_sync(0xffffffff, x, 31);
        }
    }
    grid.sync();

    if (gt == 0) g_rowptr[0] = 0;
    for (int i = gt; i < NN; i += gs) g_rowptr[i + 1] += g_boff[i >> 10];
    grid.sync();

    for (int e = gt; e < NE; e += gs) {
        int d = __ldg(dst + e);
        int pos = g_rowptr[d] + atomicAdd(&g_cur[d], 1);
        g_csr[pos] = __ldg(src + e);
    }
}

__global__ void k_molptr(const int* __restrict__ mol) {
    int t = blockIdx.x * blockDim.x + threadIdx.x;
    if (t >= NN) return;
    int m1 = __ldg(mol + t);
    int m0 = (t == 0) ? -1 : __ldg(mol + t - 1);
    for (int m = m0 + 1; m <= m1; m++) g_molptr[m] = t;
    if (t == NN - 1)
        for (int m = m1 + 1; m <= NM; m++) g_molptr[m] = NN;
}

// ============================================================================
// Unified persistent GEMM kernel: RPB-row tiles, 3 rows x 8 cols per thread,
// grid-stride over tiles. NPASS==1 preloads W once per block.
// ============================================================================
template<int GATHER, int IN_BN, int OUT_RELU, int STATS, int NPASS>
__global__ __launch_bounds__(256, 5) void k_gemm(
    const float* __restrict__ X, const float* __restrict__ W,
    const float* __restrict__ bias, float* __restrict__ O, int rows,
    const float* __restrict__ statsIn, float* __restrict__ statsOut,
    const float* __restrict__ gg, const float* __restrict__ be, float inv_n,
    size_t xStride, size_t wStride)
{
    extern __shared__ __align__(16) float dsm[];
    float* Hs = dsm;                    // RPB * HS
    float* Ws = dsm + RPB * HS;         // D * D
    __shared__ float ssa[D], ssb[D];
    int tid = threadIdx.x;
    int lane = tid & 31, cgp = tid >> 5;        // 8 column groups

    if (IN_BN && tid < D) {
        float mu  = statsIn[tid] * inv_n;
        float var = statsIn[D + tid] * inv_n - mu * mu;
        float rs  = rsqrtf(var + BN_EPS);
        float a   = rs * gg[tid];
        ssa[tid] = a; ssb[tid] = be[tid] - mu * a;
    }
    if (NPASS == 1) {
        for (int i = tid; i < D * D / 4; i += 256)
            ((float4*)Ws)[i] = ((const float4*)W)[i];
    }

    int tiles = (rows + RPB - 1) / RPB;
    for (int tile = blockIdx.x; tile < tiles; tile += gridDim.x) {
        int base = tile * RPB;
        ull a0[4], a1[4], a2[4];

        for (int ps = 0; ps < NPASS; ps++) {
            __syncthreads();    // Hs (and Ws for NPASS>1) safe to rewrite
            if (NPASS > 1) {
                const float* Wp = W + (size_t)ps * wStride;
                for (int i = tid; i < D * D / 4; i += 256)
                    ((float4*)Ws)[i] = ((const float4*)Wp)[i];
            }

            // stage Hs
            if (GATHER) {
                int c = (tid & 15) << 2;
                #pragma unroll
                for (int b = 0; b < RPB / 16; b++) {
                    int n = b * 16 + (tid >> 4);          // 0..RPB-1
                    int node = base + n;
                    if (node < rows) {
                        int beg = g_rowptr[node], end = g_rowptr[node + 1];
                        float4 acc = *(const float4*)(X + (size_t)node * D + c);
                        float4 acc2 = make_float4(0.f, 0.f, 0.f, 0.f);
                        int e = beg;
                        for (; e + 3 < end; e += 4) {
                            int s0 = __ldg(&g_csr[e]),     s1 = __ldg(&g_csr[e + 1]);
                            int s2 = __ldg(&g_csr[e + 2]), s3 = __ldg(&g_csr[e + 3]);
                            float4 v0 = *(const float4*)(X + (size_t)s0 * D + c);
                            float4 v1 = *(const float4*)(X + (size_t)s1 * D + c);
                            float4 v2 = *(const float4*)(X + (size_t)s2 * D + c);
                            float4 v3 = *(const float4*)(X + (size_t)s3 * D + c);
                            acc.x  += v0.x + v1.x; acc.y  += v0.y + v1.y;
                            acc.z  += v0.z + v1.z; acc.w  += v0.w + v1.w;
                            acc2.x += v2.x + v3.x; acc2.y += v2.y + v3.y;
                            acc2.z += v2.z + v3.z; acc2.w += v2.w + v3.w;
                        }
                        for (; e < end; e++) {
                            int s0 = __ldg(&g_csr[e]);
                            float4 v0 = *(const float4*)(X + (size_t)s0 * D + c);
                            acc.x += v0.x; acc.y += v0.y; acc.z += v0.z; acc.w += v0.w;
                        }
                        acc.x += acc2.x; acc.y += acc2.y; acc.z += acc2.z; acc.w += acc2.w;
                        *(float4*)(Hs + n * HS + c) = acc;
                    }
                }
            } else {
                const float* Xp = X + (size_t)ps * xStride;
                #pragma unroll
                for (int it = 0; it < RPB * 16 / 256; it++) {
                    int i = it * 256 + tid;
                    int r = i >> 4, c = (i & 15) << 2;
                    int row = base + r;
                    if (row < rows) {
                        float4 v = *(const float4*)(Xp + (size_t)row * D + c);
                        if (IN_BN) {
                            v.x = fmaxf(v.x * ssa[c]   + ssb[c],   0.f);
                            v.y = fmaxf(v.y * ssa[c+1] + ssb[c+1], 0.f);
                            v.z = fmaxf(v.z * ssa[c+2] + ssb[c+2], 0.f);
                            v.w = fmaxf(v.w * ssa[c+3] + ssb[c+3], 0.f);
                        }
                        *(float4*)(Hs + r * HS + c) = v;
                    }
                }
            }
            __syncthreads();

            if (ps == 0) {
                const ull* bu = (const ull*)bias;
                #pragma unroll
                for (int q = 0; q < 4; q++) {
                    a0[q] = bu[cgp * 4 + q]; a1[q] = a0[q]; a2[q] = a0[q];
                }
            }

            // GEMM: rows lane, lane+32, lane+64; cols [cgp*8, cgp*8+8)
            const float* x0p = Hs + lane * HS;
            const float* x1p = x0p + 32 * HS;
            const float* x2p = x0p + 64 * HS;
            const ulonglong2* Wu = (const ulonglong2*)Ws;
            #pragma unroll
            for (int k4 = 0; k4 < 16; k4++) {
                float4 x0 = *(const float4*)(x0p + k4 * 4);
                float4 x1 = *(const float4*)(x1p + k4 * 4);
                float4 x2 = *(const float4*)(x2p + k4 * 4);
                float h0[4] = {x0.x, x0.y, x0.z, x0.w};
                float h1[4] = {x1.x, x1.y, x1.z, x1.w};
                float h2[4] = {x2.x, x2.y, x2.z, x2.w};
                #pragma unroll
                for (int j = 0; j < 4; j++) {
                    int k = k4 * 4 + j;
                    ulonglong2 w0 = Wu[k * 16 + cgp * 2];       // warp broadcast
                    ulonglong2 w1 = Wu[k * 16 + cgp * 2 + 1];
                    ull p0 = pack2(h0[j]), p1 = pack2(h1[j]), p2 = pack2(h2[j]);
                    a0[0] = ffma2(p0, w0.x, a0[0]); a0[1] = ffma2(p0, w0.y, a0[1]);
                    a0[2] = ffma2(p0, w1.x, a0[2]); a0[3] = ffma2(p0, w1.y, a0[3]);
                    a1[0] = ffma2(p1, w0.x, a1[0]); a1[1] = ffma2(p1, w0.y, a1[1]);
                    a1[2] = ffma2(p1, w1.x, a1[2]); a1[3] = ffma2(p1, w1.y, a1[3]);
                    a2[0] = ffma2(p2, w0.x, a2[0]); a2[1] = ffma2(p2, w0.y, a2[1]);
                    a2[2] = ffma2(p2, w1.x, a2[2]); a2[3] = ffma2(p2, w1.y, a2[3]);
                }
            }
        }

        // store output
        ull* aa[3] = {a0, a1, a2};
        #pragma unroll
        for (int ri = 0; ri < 3; ri++) {
            int row = base + lane + ri * 32;
            if (row < rows) {
                ull* orow = (ull*)O + (size_t)row * 32 + cgp * 4;
                #pragma unroll
                for (int q = 0; q < 4; q++) {
                    ull v = aa[ri][q];
                    if (OUT_RELU) {
                        float2 f = u2f(v);
                        float2 g2 = make_float2(fmaxf(f.x, 0.f), fmaxf(f.y, 0.f));
                        ull t; asm("mov.b64 %0, {%1, %2};" : "=l"(t) : "f"(g2.x), "f"(g2.y));
                        v = t;
                    }
                    orow[q] = v;
                }
            }
        }

        if (STATS) {
            float s[8], ss[8];
            #pragma unroll
            for (int q = 0; q < 8; q++) { s[q] = 0.f; ss[q] = 0.f; }
            #pragma unroll
            for (int ri = 0; ri < 3; ri++) {
                bool v = (base + lane + ri * 32) < rows;
                #pragma unroll
                for (int q = 0; q < 4; q++) {
                    float2 f = u2f(aa[ri][q]);
                    if (!v) { f.x = 0.f; f.y = 0.f; }
                    s [2*q]   += f.x;       s [2*q+1] += f.y;
                    ss[2*q]   += f.x * f.x; ss[2*q+1] += f.y * f.y;
                }
            }
            #pragma unroll
            for (int off = 16; off > 0; off >>= 1) {
                #pragma unroll
                for (int q = 0; q < 8; q++) {
                    s[q]  += __shfl_xor_sync(0xffffffff, s[q],  off);
                    ss[q] += __shfl_xor_sync(0xffffffff, ss[q], off);
                }
            }
            if (lane == 0) {
                #pragma unroll
                for (int q = 0; q < 8; q++) atomicAdd(&statsOut[cgp * 8 + q], s[q]);
            } else if (lane == 1) {
                #pragma unroll
                for (int q = 0; q < 8; q++) atomicAdd(&statsOut[D + cgp * 8 + q], ss[q]);
            }
        }
    }
}

// segmented pool
__global__ void k_pool_seg(const float* __restrict__ XJ) {
    int t = blockIdx.x * 256 + threadIdx.x;
    int m = t >> 4;
    if (m >= NM) return;
    int c = (t & 15) << 2;
    int beg = g_molptr[m], end = g_molptr[m + 1];
    float4 acc = make_float4(0.f, 0.f, 0.f, 0.f);
    for (int n = beg; n < end; n++) {
        float4 v = *(const float4*)(XJ + (size_t)n * D + c);
        acc.x += v.x; acc.y += v.y; acc.z += v.z; acc.w += v.w;
    }
    *(float4*)(g_G + (size_t)m * D + c) = acc;
}

// out = relu(TG*bn) @ (W2 @ oW) + (b2 @ oW + ob)
__global__ __launch_bounds__(256) void k_final(
    const float* __restrict__ W2, const float* __restrict__ oW,
    const float* __restrict__ b2, const float* __restrict__ ob,
    const float* __restrict__ gg, const float* __restrict__ be,
    float* __restrict__ out, int rows)
{
    __shared__ float Ws[D * NO];
    __shared__ float bcs[NO], sa[D], sb[D];
    int tid = threadIdx.x;
    const float* statsIn = g_stats + 3 * 2 * D;
    for (int i = tid; i < D * NO; i += 256) {
        int k = i / NO, o = i % NO;
        float sum = 0.f;
        for (int j = 0; j < D; j++) sum += W2[k * D + j] * oW[j * NO + o];
        Ws[i] = sum;
    }
    if (tid < NO) {
        float sum = ob[tid];
        for (int j = 0; j < D; j++) sum += b2[j] * oW[j * NO + tid];
        bcs[tid] = sum;
    }
    if (tid < D) {
        float mu  = statsIn[tid] * (1.0f / NM);
        float var = statsIn[D + tid] * (1.0f / NM) - mu * mu;
        float rs  = rsqrtf(var + BN_EPS);
        float a   = rs * gg[tid];
        sa[tid] = a; sb[tid] = be[tid] - mu * a;
    }
    __syncthreads();
    int row = blockIdx.x * 256 + tid;
    if (row >= rows) return;
    float acc[NO];
    #pragma unroll
    for (int o = 0; o < NO; o++) acc[o] = bcs[o];
    const float* tr = g_TG + (size_t)row * D;
    for (int k = 0; k < D; k++) {
        float h = fmaxf(tr[k] * sa[k] + sb[k], 0.f);
        #pragma unroll
        for (int o = 0; o < NO; o++) acc[o] += h * Ws[k * NO + o];
    }
    float* orow = out + (size_t)row * NO;
    #pragma unroll
    for (int o = 0; o < NO; o++) orow[o] = acc[o];
}

// ---------------- host ----------------
extern "C" void kernel_launch(void* const* d_in, const int* in_sizes, int n_in,
                              void* d_out, int out_size)
{
    const int*   atom_ids = (const int*)  d_in[0];
    const int*   edge     = (const int*)  d_in[1];
    const int*   mol_ids  = (const int*)  d_in[2];
    const float* emb_W    = (const float*)d_in[3];
    const float* gin_W1   = (const float*)d_in[4];
    const float* gin_b1   = (const float*)d_in[5];
    const float* gin_g1   = (const float*)d_in[6];
    const float* gin_be1  = (const float*)d_in[7];
    const float* gin_W2   = (const float*)d_in[8];
    const float* gin_b2   = (const float*)d_in[9];
    const float* jk_W     = (const float*)d_in[10];
    const float* jk_b     = (const float*)d_in[11];
    const float* ffn_W1   = (const float*)d_in[12];
    const float* ffn_b1   = (const float*)d_in[13];
    const float* ffn_g    = (const float*)d_in[14];
    const float* ffn_be   = (const float*)d_in[15];
    const float* ffn_W2   = (const float*)d_in[16];
    const float* ffn_b2   = (const float*)d_in[17];
    const float* out_W    = (const float*)d_in[18];
    const float* out_b    = (const float*)d_in[19];
    float* out = (float*)d_out;

    const int* src = edge;
    const int* dst = edge + NE;

    float *X0, *T, *XS, *G, *TG, *stats;
    cudaGetSymbolAddress((void**)&X0,    g_X0);
    cudaGetSymbolAddress((void**)&T,     g_T);
    cudaGetSymbolAddress((void**)&XS,    g_XS);
    cudaGetSymbolAddress((void**)&G,     g_G);
    cudaGetSymbolAddress((void**)&TG,    g_TG);
    cudaGetSymbolAddress((void**)&stats, g_stats);

    cudaFuncSetAttribute(k_gemm<1,0,0,1,1>, cudaFuncAttributeMaxDynamicSharedMemorySize, SMEM_G);
    cudaFuncSetAttribute(k_gemm<0,1,1,0,1>, cudaFuncAttributeMaxDynamicSharedMemorySize, SMEM_G);
    cudaFuncSetAttribute(k_gemm<0,0,0,0,NL>, cudaFuncAttributeMaxDynamicSharedMemorySize, SMEM_G);
    cudaFuncSetAttribute(k_gemm<0,0,0,1,1>, cudaFuncAttributeMaxDynamicSharedMemorySize, SMEM_G);

    k_init<<<(NN + 255)/256, 256>>>();
    k_embed<<<(NN*16 + 255)/256, 256>>>(atom_ids, emb_W);
    {
        void* args[] = { (void*)&src, (void*)&dst };
        cudaLaunchCooperativeKernel((void*)k_csr_coop, dim3(COOP_BLOCKS), dim3(256),
                                    args, 0, (cudaStream_t)0);
    }

    const int TILES = (NN + RPB - 1) / RPB;
    const int GRID  = (TILES < PGRID) ? TILES : PGRID;
    for (int l = 0; l < NL; l++) {
        const float* xin = (l == 0) ? X0 : XS + (size_t)(l-1) * NN * D;
        float* slot = stats + (size_t)l * 2 * D;
        // gemm1: gather + GEMM + stats  -> T
        k_gemm<1,0,0,1,1><<<GRID, 256, SMEM_G>>>(
            xin, gin_W1 + (size_t)l*D*D, gin_b1 + l*D, T, NN,
            nullptr, slot, nullptr, nullptr, 0.f, 0, 0);
        // gemm2: BN+relu stage + GEMM + relu -> XS[l]
        k_gemm<0,1,1,0,1><<<GRID, 256, SMEM_G>>>(
            T, gin_W2 + (size_t)l*D*D, gin_b2 + l*D, XS + (size_t)l*NN*D, NN,
            slot, nullptr, gin_g1 + l*D, gin_be1 + l*D, 1.0f / NN, 0, 0);
    }

    k_molptr<<<(NN + 255)/256, 256>>>(mol_ids);
    // JK: 3-pass accumulate -> X0
    k_gemm<0,0,0,0,NL><<<GRID, 256, SMEM_G>>>(
        XS, jk_W, jk_b, X0, NN,
        nullptr, nullptr, nullptr, nullptr, 0.f, (size_t)NN * D, (size_t)D * D);

    k_pool_seg<<<(NM*16 + 255)/256, 256>>>(X0);

    float* slot3 = stats + 3 * 2 * D;
    const int TILES_M = (NM + RPB - 1) / RPB;
    k_gemm<0,0,0,1,1><<<TILES_M, 256, SMEM_G>>>(
        G, ffn_W1, ffn_b1, TG, NM,
        nullptr, slot3, nullptr, nullptr, 0.f, 0, 0);

    k_final<<<(NM + 255)/256, 256>>>(ffn_W2, out_W, ffn_b2, out_b,
                                     ffn_g, ffn_be, out, NM);
}

// round 11
// speedup vs baseline: 1.1127x; 1.1127x over previous
#include <cuda_runtime.h>
#include <cooperative_groups.h>
namespace cg = cooperative_groups;

#define NN 100000
#define NE 1200000
#define D 64
#define NL 3
#define NM 5000
#define NO 24
#define BN_EPS 1e-5f
#define NB_SCAN ((NN + 1023) / 1024)
#define HS 68          // smem row stride (floats): 272B, float4-aligned, conflict-free
#define RPB 128        // rows per block in unified GEMM
#define COOP_BLOCKS 592
#define SMEM_G ((RPB * HS + D * D) * 4)   // 51200 B dynamic

typedef unsigned long long ull;

// ---------------- scratch ----------------
__device__ __align__(128) float g_X0 [NN * D];
__device__ __align__(128) float g_T  [NN * D];
__device__ __align__(128) float g_XS [NL * NN * D];
__device__ __align__(128) float g_G  [NM * D];
__device__ __align__(128) float g_TG [NM * D];
__device__ __align__(128) float g_stats[4 * 2 * D];
__device__ __align__(128) int g_deg   [NN];
__device__ __align__(128) int g_cur   [NN];
__device__ __align__(128) int g_rowptr[NN + 1];
__device__ __align__(128) int g_csr   [NE];
__device__ __align__(128) int g_bsum  [NB_SCAN];
__device__ __align__(128) int g_boff  [NB_SCAN];
__device__ __align__(128) int g_molptr[NM + 1];

// ---------------- f32x2 helpers ----------------
__device__ __forceinline__ ull ffma2(ull a, ull b, ull c) {
    ull d; asm("fma.rn.f32x2 %0, %1, %2, %3;" : "=l"(d) : "l"(a), "l"(b), "l"(c));
    return d;
}
__device__ __forceinline__ ull pack2(float x) {
    ull r; asm("mov.b64 %0, {%1, %1};" : "=l"(r) : "f"(x)); return r;
}
__device__ __forceinline__ float2 u2f(ull v) {
    float2 f; asm("mov.b64 {%0, %1}, %2;" : "=f"(f.x), "=f"(f.y) : "l"(v)); return f;
}

// ---------------- init ----------------
__global__ void k_init() {
    int t = blockIdx.x * blockDim.x + threadIdx.x;
    if (t < NN) { g_deg[t] = 0; g_cur[t] = 0; }
    if (t < 4 * 2 * D) g_stats[t] = 0.f;
}

__global__ void k_embed(const int* __restrict__ atom_ids, const float* __restrict__ embW) {
    int t = blockIdx.x * blockDim.x + threadIdx.x;
    if (t >= NN * 16) return;
    int n = t >> 4, c = (t & 15) << 2;
    int a = __ldg(atom_ids + n);
    *(float4*)(g_X0 + (size_t)n * D + c) = *(const float4*)(embW + (size_t)a * D + c);
}

// ---------------- cooperative CSR build -----------------
__global__ void k_csr_coop(const int* __restrict__ src, const int* __restrict__ dst) {
    cg::grid_group grid = cg::this_grid();
    int tid = threadIdx.x, bid = blockIdx.x;
    int gt = bid * 256 + tid, gs = gridDim.x * 256;

    for (int e = gt; e < NE; e += gs) atomicAdd(&g_deg[__ldg(dst + e)], 1);
    grid.sync();

    __shared__ int sh[256];
    if (bid < NB_SCAN) {
        int base = bid * 1024;
        int loc[4]; int s = 0;
        #pragma unroll
        for (int j = 0; j < 4; j++) {
            int i = base + tid * 4 + j;
            int v = (i < NN) ? g_deg[i] : 0;
            s += v; loc[j] = s;
        }
        int excl_in = s;
        sh[tid] = excl_in; __syncthreads();
        for (int off = 1; off < 256; off <<= 1) {
            int t2 = (tid >= off) ? sh[tid - off] : 0;
            __syncthreads();
            sh[tid] += t2;
            __syncthreads();
        }
        int pre = sh[tid] - excl_in;
        #pragma unroll
        for (int j = 0; j < 4; j++) {
            int i = base + tid * 4 + j;
            if (i < NN) g_rowptr[i + 1] = pre + loc[j];
        }
        if (tid == 255) g_bsum[bid] = sh[255];
    }
    grid.sync();

    if (bid == 0 && tid < 32) {
        int carry = 0;
        for (int b = 0; b < NB_SCAN; b += 32) {
            int idx = b + tid;
            int v = (idx < NB_SCAN) ? g_bsum[idx] : 0;
            int x = v;
            #pragma unroll
            for (int off = 1; off < 32; off <<= 1) {
                int y = __shfl_up_sync(0xffffffff, x, off);
                if (tid >= off) x += y;
            }
            if (idx < NB_SCAN) g_boff[idx] = carry + x - v;
            carry += __shfl_sync(0xffffffff, x, 31);
        }
    }
    grid.sync();

    if (gt == 0) g_rowptr[0] = 0;
    for (int i = gt; i < NN; i += gs) g_rowptr[i + 1] += g_boff[i >> 10];
    grid.sync();

    for (int e = gt; e < NE; e += gs) {
        int d = __ldg(dst + e);
        int pos = g_rowptr[d] + atomicAdd(&g_cur[d], 1);
        g_csr[pos] = __ldg(src + e);
    }
}

__global__ void k_molptr(const int* __restrict__ mol) {
    int t = blockIdx.x * blockDim.x + threadIdx.x;
    if (t >= NN) return;
    int m1 = __ldg(mol + t);
    int m0 = (t == 0) ? -1 : __ldg(mol + t - 1);
    for (int m = m0 + 1; m <= m1; m++) g_molptr[m] = t;
    if (t == NN - 1)
        for (int m = m1 + 1; m <= NM; m++) g_molptr[m] = NN;
}

// ============================================================================
// Unified GEMM kernel: 128 rows/block, 4 rows x 8 cols per thread.
//   R8 configuration + smem-staged rowptr (removes one dependent-load level).
// ============================================================================
template<int GATHER, int IN_BN, int OUT_RELU, int STATS, int NPASS>
__global__ __launch_bounds__(256) void k_gemm(
    const float* __restrict__ X, const float* __restrict__ W,
    const float* __restrict__ bias, float* __restrict__ O, int rows,
    const float* __restrict__ statsIn, float* __restrict__ statsOut,
    const float* __restrict__ gg, const float* __restrict__ be, float inv_n,
    size_t xStride, size_t wStride)
{
    extern __shared__ __align__(16) float dsm[];
    float* Hs = dsm;                    // RPB * HS
    float* Ws = dsm + RPB * HS;         // D * D
    __shared__ float ssa[D], ssb[D];
    __shared__ int   rp[RPB + 1];
    int tid = threadIdx.x;
    int base = blockIdx.x * RPB;
    int lane = tid & 31, cgp = tid >> 5;        // 8 column groups

    if (IN_BN && tid < D) {
        float mu  = statsIn[tid] * inv_n;
        float var = statsIn[D + tid] * inv_n - mu * mu;
        float rs  = rsqrtf(var + BN_EPS);
        float a   = rs * gg[tid];
        ssa[tid] = a; ssb[tid] = be[tid] - mu * a;
    }
    if (GATHER) {
        // stage rowptr for the tile (one latency round, read many times)
        if (tid <= RPB) {
            int node = base + tid;
            rp[tid] = (node <= rows) ? __ldg(&g_rowptr[node]) : 0;
        }
    }

    ull a0[4], a1[4], a2[4], a3[4];
    const ull* bu = (const ull*)bias;
    #pragma unroll
    for (int q = 0; q < 4; q++) {
        a0[q] = bu[cgp * 4 + q]; a1[q] = a0[q]; a2[q] = a0[q]; a3[q] = a0[q];
    }

    for (int ps = 0; ps < NPASS; ps++) {
        __syncthreads();
        // load W pass
        const float* Wp = W + (size_t)ps * wStride;
        for (int i = tid; i < D * D / 4; i += 256)
            ((float4*)Ws)[i] = ((const float4*)Wp)[i];

        // stage Hs
        if (GATHER) {
            int c = (tid & 15) << 2;
            #pragma unroll
            for (int b = 0; b < 8; b++) {
                int n = b * 16 + (tid >> 4);          // 0..127
                int node = base + n;
                if (node < rows) {
                    int beg = rp[n], end = rp[n + 1];
                    float4 acc = *(const float4*)(X + (size_t)node * D + c);
                    float4 acc2 = make_float4(0.f, 0.f, 0.f, 0.f);
                    int e = beg;
                    for (; e + 3 < end; e += 4) {
                        int s0 = __ldg(&g_csr[e]),     s1 = __ldg(&g_csr[e + 1]);
                        int s2 = __ldg(&g_csr[e + 2]), s3 = __ldg(&g_csr[e + 3]);
                        float4 v0 = *(const float4*)(X + (size_t)s0 * D + c);
                        float4 v1 = *(const float4*)(X + (size_t)s1 * D + c);
                        float4 v2 = *(const float4*)(X + (size_t)s2 * D + c);
                        float4 v3 = *(const float4*)(X + (size_t)s3 * D + c);
                        acc.x  += v0.x + v1.x; acc.y  += v0.y + v1.y;
                        acc.z  += v0.z + v1.z; acc.w  += v0.w + v1.w;
                        acc2.x += v2.x + v3.x; acc2.y += v2.y + v3.y;
                        acc2.z += v2.z + v3.z; acc2.w += v2.w + v3.w;
                    }
                    for (; e < end; e++) {
                        int s0 = __ldg(&g_csr[e]);
                        float4 v0 = *(const float4*)(X + (size_t)s0 * D + c);
                        acc.x += v0.x; acc.y += v0.y; acc.z += v0.z; acc.w += v0.w;
                    }
                    acc.x += acc2.x; acc.y += acc2.y; acc.z += acc2.z; acc.w += acc2.w;
                    *(float4*)(Hs + n * HS + c) = acc;
                }
            }
        } else {
            const float* Xp = X + (size_t)ps * xStride;
            #pragma unroll
            for (int it = 0; it < RPB * 16 / 256; it++) {
                int i = it * 256 + tid;
                int r = i >> 4, c = (i & 15) << 2;
                int row = base + r;
                if (row < rows) {
                    float4 v = *(const float4*)(Xp + (size_t)row * D + c);
                    if (IN_BN) {
                        v.x = fmaxf(v.x * ssa[c]   + ssb[c],   0.f);
                        v.y = fmaxf(v.y * ssa[c+1] + ssb[c+1], 0.f);
                        v.z = fmaxf(v.z * ssa[c+2] + ssb[c+2], 0.f);
                        v.w = fmaxf(v.w * ssa[c+3] + ssb[c+3], 0.f);
                    }
                    *(float4*)(Hs + r * HS + c) = v;
                }
            }
        }
        __syncthreads();

        // GEMM: rows lane, lane+32, lane+64, lane+96; cols [cgp*8, cgp*8+8)
        const float* x0p = Hs + lane * HS;
        const float* x1p = x0p + 32 * HS;
        const float* x2p = x0p + 64 * HS;
        const float* x3p = x0p + 96 * HS;
        const ulonglong2* Wu = (const ulonglong2*)Ws;
        #pragma unroll
        for (int k4 = 0; k4 < 16; k4++) {
            float4 x0 = *(const float4*)(x0p + k4 * 4);
            float4 x1 = *(const float4*)(x1p + k4 * 4);
            float4 x2 = *(const float4*)(x2p + k4 * 4);
            float4 x3 = *(const float4*)(x3p + k4 * 4);
            float h0[4] = {x0.x, x0.y, x0.z, x0.w};
            float h1[4] = {x1.x, x1.y, x1.z, x1.w};
            float h2[4] = {x2.x, x2.y, x2.z, x2.w};
            float h3[4] = {x3.x, x3.y, x3.z, x3.w};
            #pragma unroll
            for (int j = 0; j < 4; j++) {
                int k = k4 * 4 + j;
                ulonglong2 w0 = Wu[k * 16 + cgp * 2];       // broadcast in warp
                ulonglong2 w1 = Wu[k * 16 + cgp * 2 + 1];
                ull p0 = pack2(h0[j]), p1 = pack2(h1[j]);
                ull p2 = pack2(h2[j]), p3 = pack2(h3[j]);
                a0[0] = ffma2(p0, w0.x, a0[0]); a0[1] = ffma2(p0, w0.y, a0[1]);
                a0[2] = ffma2(p0, w1.x, a0[2]); a0[3] = ffma2(p0, w1.y, a0[3]);
                a1[0] = ffma2(p1, w0.x, a1[0]); a1[1] = ffma2(p1, w0.y, a1[1]);
                a1[2] = ffma2(p1, w1.x, a1[2]); a1[3] = ffma2(p1, w1.y, a1[3]);
                a2[0] = ffma2(p2, w0.x, a2[0]); a2[1] = ffma2(p2, w0.y, a2[1]);
                a2[2] = ffma2(p2, w1.x, a2[2]); a2[3] = ffma2(p2, w1.y, a2[3]);
                a3[0] = ffma2(p3, w0.x, a3[0]); a3[1] = ffma2(p3, w0.y, a3[1]);
                a3[2] = ffma2(p3, w1.x, a3[2]); a3[3] = ffma2(p3, w1.y, a3[3]);
            }
        }
    }

    // store output
    ull* aa[4] = {a0, a1, a2, a3};
    #pragma unroll
    for (int ri = 0; ri < 4; ri++) {
        int row = base + lane + ri * 32;
        if (row < rows) {
            ull* orow = (ull*)O + (size_t)row * 32 + cgp * 4;
            #pragma unroll
            for (int q = 0; q < 4; q++) {
                ull v = aa[ri][q];
                if (OUT_RELU) {
                    float2 f = u2f(v);
                    float2 g2 = make_float2(fmaxf(f.x, 0.f), fmaxf(f.y, 0.f));
                    ull t; asm("mov.b64 %0, {%1, %2};" : "=l"(t) : "f"(g2.x), "f"(g2.y));
                    v = t;
                }
                orow[q] = v;
            }
        }
    }

    if (STATS) {
        float s[8], ss[8];
        #pragma unroll
        for (int q = 0; q < 8; q++) { s[q] = 0.f; ss[q] = 0.f; }
        #pragma unroll
        for (int ri = 0; ri < 4; ri++) {
            bool v = (base + lane + ri * 32) < rows;
            #pragma unroll
            for (int q = 0; q < 4; q++) {
                float2 f = u2f(aa[ri][q]);
                if (!v) { f.x = 0.f; f.y = 0.f; }
                s [2*q]   += f.x;       s [2*q+1] += f.y;
                ss[2*q]   += f.x * f.x; ss[2*q+1] += f.y * f.y;
            }
        }
        #pragma unroll
        for (int off = 16; off > 0; off >>= 1) {
            #pragma unroll
            for (int q = 0; q < 8; q++) {
                s[q]  += __shfl_xor_sync(0xffffffff, s[q],  off);
                ss[q] += __shfl_xor_sync(0xffffffff, ss[q], off);
            }
        }
        if (lane == 0) {
            #pragma unroll
            for (int q = 0; q < 8; q++) atomicAdd(&statsOut[cgp * 8 + q], s[q]);
        } else if (lane == 1) {
            #pragma unroll
            for (int q = 0; q < 8; q++) atomicAdd(&statsOut[D + cgp * 8 + q], ss[q]);
        }
    }
}

// segmented pool
__global__ void k_pool_seg(const float* __restrict__ XJ) {
    int t = blockIdx.x * 256 + threadIdx.x;
    int m = t >> 4;
    if (m >= NM) return;
    int c = (t & 15) << 2;
    int beg = g_molptr[m], end = g_molptr[m + 1];
    float4 acc = make_float4(0.f, 0.f, 0.f, 0.f);
    for (int n = beg; n < end; n++) {
        float4 v = *(const float4*)(XJ + (size_t)n * D + c);
        acc.x += v.x; acc.y += v.y; acc.z += v.z; acc.w += v.w;
    }
    *(float4*)(g_G + (size_t)m * D + c) = acc;
}

// out = relu(TG*bn) @ (W2 @ oW) + (b2 @ oW + ob)
__global__ __launch_bounds__(256) void k_final(
    const float* __restrict__ W2, const float* __restrict__ oW,
    const float* __restrict__ b2, const float* __restrict__ ob,
    const float* __restrict__ gg, const float* __restrict__ be,
    float* __restrict__ out, int rows)
{
    __shared__ float Ws[D * NO];
    __shared__ float bcs[NO], sa[D], sb[D];
    int tid = threadIdx.x;
    const float* statsIn = g_stats + 3 * 2 * D;
    for (int i = tid; i < D * NO; i += 256) {
        int k = i / NO, o = i % NO;
        float sum = 0.f;
        for (int j = 0; j < D; j++) sum += W2[k * D + j] * oW[j * NO + o];
        Ws[i] = sum;
    }
    if (tid < NO) {
        float sum = ob[tid];
        for (int j = 0; j < D; j++) sum += b2[j] * oW[j * NO + tid];
        bcs[tid] = sum;
    }
    if (tid < D) {
        float mu  = statsIn[tid] * (1.0f / NM);
        float var = statsIn[D + tid] * (1.0f / NM) - mu * mu;
        float rs  = rsqrtf(var + BN_EPS);
        float a   = rs * gg[tid];
        sa[tid] = a; sb[tid] = be[tid] - mu * a;
    }
    __syncthreads();
    int row = blockIdx.x * 256 + tid;
    if (row >= rows) return;
    float acc[NO];
    #pragma unroll
    for (int o = 0; o < NO; o++) acc[o] = bcs[o];
    const float* tr = g_TG + (size_t)row * D;
    for (int k = 0; k < D; k++) {
        float h = fmaxf(tr[k] * sa[k] + sb[k], 0.f);
        #pragma unroll
        for (int o = 0; o < NO; o++) acc[o] += h * Ws[k * NO + o];
    }
    float* orow = out + (size_t)row * NO;
    #pragma unroll
    for (int o = 0; o < NO; o++) orow[o] = acc[o];
}

// ---------------- host ----------------
extern "C" void kernel_launch(void* const* d_in, const int* in_sizes, int n_in,
                              void* d_out, int out_size)
{
    const int*   atom_ids = (const int*)  d_in[0];
    const int*   edge     = (const int*)  d_in[1];
    const int*   mol_ids  = (const int*)  d_in[2];
    const float* emb_W    = (const float*)d_in[3];
    const float* gin_W1   = (const float*)d_in[4];
    const float* gin_b1   = (const float*)d_in[5];
    const float* gin_g1   = (const float*)d_in[6];
    const float* gin_be1  = (const float*)d_in[7];
    const float* gin_W2   = (const float*)d_in[8];
    const float* gin_b2   = (const float*)d_in[9];
    const float* jk_W     = (const float*)d_in[10];
    const float* jk_b     = (const float*)d_in[11];
    const float* ffn_W1   = (const float*)d_in[12];
    const float* ffn_b1   = (const float*)d_in[13];
    const float* ffn_g    = (const float*)d_in[14];
    const float* ffn_be   = (const float*)d_in[15];
    const float* ffn_W2   = (const float*)d_in[16];
    const float* ffn_b2   = (const float*)d_in[17];
    const float* out_W    = (const float*)d_in[18];
    const float* out_b    = (const float*)d_in[19];
    float* out = (float*)d_out;

    const int* src = edge;
    const int* dst = edge + NE;

    float *X0, *T, *XS, *G, *TG, *stats;
    cudaGetSymbolAddress((void**)&X0,    g_X0);
    cudaGetSymbolAddress((void**)&T,     g_T);
    cudaGetSymbolAddress((void**)&XS,    g_XS);
    cudaGetSymbolAddress((void**)&G,     g_G);
    cudaGetSymbolAddress((void**)&TG,    g_TG);
    cudaGetSymbolAddress((void**)&stats, g_stats);

    cudaFuncSetAttribute(k_gemm<1,0,0,1,1>, cudaFuncAttributeMaxDynamicSharedMemorySize, SMEM_G);
    cudaFuncSetAttribute(k_gemm<0,1,1,0,1>, cudaFuncAttributeMaxDynamicSharedMemorySize, SMEM_G);
    cudaFuncSetAttribute(k_gemm<0,0,0,0,NL>, cudaFuncAttributeMaxDynamicSharedMemorySize, SMEM_G);
    cudaFuncSetAttribute(k_gemm<0,0,0,1,1>, cudaFuncAttributeMaxDynamicSharedMemorySize, SMEM_G);

    k_init<<<(NN + 255)/256, 256>>>();
    k_embed<<<(NN*16 + 255)/256, 256>>>(atom_ids, emb_W);
    {
        void* args[] = { (void*)&src, (void*)&dst };
        cudaLaunchCooperativeKernel((void*)k_csr_coop, dim3(COOP_BLOCKS), dim3(256),
                                    args, 0, (cudaStream_t)0);
    }

    const int GRID = (NN + RPB - 1) / RPB;
    for (int l = 0; l < NL; l++) {
        const float* xin = (l == 0) ? X0 : XS + (size_t)(l-1) * NN * D;
        float* slot = stats + (size_t)l * 2 * D;
        // gemm1: gather + GEMM + stats  -> T
        k_gemm<1,0,0,1,1><<<GRID, 256, SMEM_G>>>(
            xin, gin_W1 + (size_t)l*D*D, gin_b1 + l*D, T, NN,
            nullptr, slot, nullptr, nullptr, 0.f, 0, 0);
        // gemm2: BN+relu stage + GEMM + relu -> XS[l]
        k_gemm<0,1,1,0,1><<<GRID, 256, SMEM_G>>>(
            T, gin_W2 + (size_t)l*D*D, gin_b2 + l*D, XS + (size_t)l*NN*D, NN,
            slot, nullptr, gin_g1 + l*D, gin_be1 + l*D, 1.0f / NN, 0, 0);
    }

    k_molptr<<<(NN + 255)/256, 256>>>(mol_ids);
    // JK: 3-pass accumulate -> X0
    k_gemm<0,0,0,0,NL><<<GRID, 256, SMEM_G>>>(
        XS, jk_W, jk_b, X0, NN,
        nullptr, nullptr, nullptr, nullptr, 0.f, (size_t)NN * D, (size_t)D * D);

    k_pool_seg<<<(NM*16 + 255)/256, 256>>>(X0);

    float* slot3 = stats + 3 * 2 * D;
    k_gemm<0,0,0,1,1><<<(NM + RPB - 1)/RPB, 256, SMEM_G>>>(
        G, ffn_W1, ffn_b1, TG, NM,
        nullptr, slot3, nullptr, nullptr, 0.f, 0, 0);

    k_final<<<(NM + 255)/256, 256>>>(ffn_W2, out_W, ffn_b2, out_b,
                                     ffn_g, ffn_be, out, NM);
}

// round 12
// speedup vs baseline: 1.3962x; 1.2548x over previous
#include <cuda_runtime.h>
#include <cooperative_groups.h>
namespace cg = cooperative_groups;

#define NN 100000
#define NE 1200000
#define D 64
#define NL 3
#define NM 5000
#define NO 24
#define BN_EPS 1e-5f
#define NB_SCAN ((NN + 1023) / 1024)
#define HS 68          // smem row stride (floats): 272B, float4-aligned, conflict-free
#define RPB 128        // rows per block
#define COOP_BLOCKS 592
#define SMEM_G (RPB * HS * 4 + 2 * 2048 * 8)   // Hs + WBh + WBl = 67584 B

typedef unsigned long long ull;

// ---------------- scratch ----------------
__device__ __align__(128) float g_X0 [NN * D];
__device__ __align__(128) float g_T  [NN * D];
__device__ __align__(128) float g_XS [NL * NN * D];
__device__ __align__(128) float g_G  [NM * D];
__device__ __align__(128) float g_TG [NM * D];
__device__ __align__(128) float g_stats[4 * 2 * D];
__device__ __align__(128) int g_deg   [NN];
__device__ __align__(128) int g_cur   [NN];
__device__ __align__(128) int g_rowptr[NN + 1];
__device__ __align__(128) int g_csr   [NE];
__device__ __align__(128) int g_bsum  [NB_SCAN];
__device__ __align__(128) int g_boff  [NB_SCAN];
__device__ __align__(128) int g_molptr[NM + 1];

// ---------------- helpers ----------------
__device__ __forceinline__ uint32_t cvt_tf32(float x) {
    uint32_t r; asm("cvt.rna.tf32.f32 %0, %1;" : "=r"(r) : "f"(x)); return r;
}
__device__ __forceinline__ void mma_tf32(float* c, uint32_t a0, uint32_t a1,
                                         uint32_t a2, uint32_t a3,
                                         uint32_t b0, uint32_t b1) {
    asm volatile(
        "mma.sync.aligned.m16n8k8.row.col.f32.tf32.tf32.f32 "
        "{%0,%1,%2,%3},{%4,%5,%6,%7},{%8,%9},{%0,%1,%2,%3};"
        : "+f"(c[0]), "+f"(c[1]), "+f"(c[2]), "+f"(c[3])
        : "r"(a0), "r"(a1), "r"(a2), "r"(a3), "r"(b0), "r"(b1));
}

// ---------------- init ----------------
__global__ void k_init() {
    int t = blockIdx.x * blockDim.x + threadIdx.x;
    if (t < NN) { g_deg[t] = 0; g_cur[t] = 0; }
    if (t < 4 * 2 * D) g_stats[t] = 0.f;
}

__global__ void k_embed(const int* __restrict__ atom_ids, const float* __restrict__ embW) {
    int t = blockIdx.x * blockDim.x + threadIdx.x;
    if (t >= NN * 16) return;
    int n = t >> 4, c = (t & 15) << 2;
    int a = __ldg(atom_ids + n);
    *(float4*)(g_X0 + (size_t)n * D + c) = *(const float4*)(embW + (size_t)a * D + c);
}

// ---------------- cooperative CSR build -----------------
__global__ void k_csr_coop(const int* __restrict__ src, const int* __restrict__ dst) {
    cg::grid_group grid = cg::this_grid();
    int tid = threadIdx.x, bid = blockIdx.x;
    int gt = bid * 256 + tid, gs = gridDim.x * 256;

    for (int e = gt; e < NE; e += gs) atomicAdd(&g_deg[__ldg(dst + e)], 1);
    grid.sync();

    __shared__ int sh[256];
    if (bid < NB_SCAN) {
        int base = bid * 1024;
        int loc[4]; int s = 0;
        #pragma unroll
        for (int j = 0; j < 4; j++) {
            int i = base + tid * 4 + j;
            int v = (i < NN) ? g_deg[i] : 0;
            s += v; loc[j] = s;
        }
        int excl_in = s;
        sh[tid] = excl_in; __syncthreads();
        for (int off = 1; off < 256; off <<= 1) {
            int t2 = (tid >= off) ? sh[tid - off] : 0;
            __syncthreads();
            sh[tid] += t2;
            __syncthreads();
        }
        int pre = sh[tid] - excl_in;
        #pragma unroll
        for (int j = 0; j < 4; j++) {
            int i = base + tid * 4 + j;
            if (i < NN) g_rowptr[i + 1] = pre + loc[j];
        }
        if (tid == 255) g_bsum[bid] = sh[255];
    }
    grid.sync();

    if (bid == 0 && tid < 32) {
        int carry = 0;
        for (int b = 0; b < NB_SCAN; b += 32) {
            int idx = b + tid;
            int v = (idx < NB_SCAN) ? g_bsum[idx] : 0;
            int x = v;
            #pragma unroll
            for (int off = 1; off < 32; off <<= 1) {
                int y = __shfl_up_sync(0xffffffff, x, off);
                if (tid >= off) x += y;
            }
            if (idx < NB_SCAN) g_boff[idx] = carry + x - v;
            carry += __shfl_sync(0xffffffff, x, 31);
        }
    }
    grid.sync();

    if (gt == 0) g_rowptr[0] = 0;
    for (int i = gt; i < NN; i += gs) g_rowptr[i + 1] += g_boff[i >> 10];
    grid.sync();

    for (int e = gt; e < NE; e += gs) {
        int d = __ldg(dst + e);
        int pos = g_rowptr[d] + atomicAdd(&g_cur[d], 1);
        g_csr[pos] = __ldg(src + e);
    }
}

__global__ void k_molptr(const int* __restrict__ mol) {
    int t = blockIdx.x * blockDim.x + threadIdx.x;
    if (t >= NN) return;
    int m1 = __ldg(mol + t);
    int m0 = (t == 0) ? -1 : __ldg(mol + t - 1);
    for (int m = m0 + 1; m <= m1; m++) g_molptr[m] = t;
    if (t == NN - 1)
        for (int m = m1 + 1; m <= NM; m++) g_molptr[m] = NN;
}

// ============================================================================
// Unified GEMM kernel, tensor-core (mma.sync tf32, 3xTF32) inner loop.
// 128 rows/block, 8 warps; warp w owns rows [w*16, w*16+16) x all 64 cols.
// ============================================================================
template<int GATHER, int IN_BN, int OUT_RELU, int STATS, int NPASS>
__global__ __launch_bounds__(256) void k_gemm(
    const float* __restrict__ X, const float* __restrict__ W,
    const float* __restrict__ bias, float* __restrict__ O, int rows,
    const float* __restrict__ statsIn, float* __restrict__ statsOut,
    const float* __restrict__ gg, const float* __restrict__ be, float inv_n,
    size_t xStride, size_t wStride)
{
    extern __shared__ __align__(16) float dsm[];
    float* Hs = dsm;                         // RPB*HS floats
    ull*   WBh = (ull*)(dsm + RPB * HS);     // 2048 ull (fragment-order W hi)
    ull*   WBl = WBh + 2048;                 // 2048 ull (fragment-order W lo)
    __shared__ float ssa[D], ssb[D];
    __shared__ float sbuf[2 * D];
    __shared__ int   rp[RPB + 1];
    int tid = threadIdx.x;
    int base = blockIdx.x * RPB;
    int w = tid >> 5, l = tid & 31;
    int g = l >> 2, t = l & 3;

    if (IN_BN && tid < D) {
        float mu  = statsIn[tid] * inv_n;
        float var = statsIn[D + tid] * inv_n - mu * mu;
        float rs  = rsqrtf(var + BN_EPS);
        float a   = rs * gg[tid];
        ssa[tid] = a; ssb[tid] = be[tid] - mu * a;
    }
    if (STATS && tid < 2 * D) sbuf[tid] = 0.f;
    if (GATHER && tid <= RPB) {
        int node = base + tid;
        rp[tid] = (node <= rows) ? __ldg(&g_rowptr[node]) : 0;
    }

    // C fragments: 8 n-tiles x 4 regs. Init with bias (both row groups same col).
    float c[8][4];
    #pragma unroll
    for (int nt = 0; nt < 8; nt++) {
        float2 b2 = *(const float2*)(bias + nt * 8 + 2 * t);
        c[nt][0] = b2.x; c[nt][1] = b2.y; c[nt][2] = b2.x; c[nt][3] = b2.y;
    }

    for (int ps = 0; ps < NPASS; ps++) {
        __syncthreads();
        // ---- stage W into fragment-order hi/lo arrays ----
        {
            const float* Wp = W + (size_t)ps * wStride;
            for (int i = tid; i < 2048; i += 256) {
                int ent = i >> 5, ll = i & 31;
                int ks = ent >> 3, nt = ent & 7;
                int k0 = ks * 8 + (ll & 3), n = nt * 8 + (ll >> 2);
                float w0 = __ldg(&Wp[k0 * D + n]);
                float w1 = __ldg(&Wp[(k0 + 4) * D + n]);
                uint32_t h0 = cvt_tf32(w0), h1 = cvt_tf32(w1);
                uint32_t l0 = cvt_tf32(w0 - __uint_as_float(h0));
                uint32_t l1 = cvt_tf32(w1 - __uint_as_float(h1));
                WBh[i] = (ull)h0 | ((ull)h1 << 32);
                WBl[i] = (ull)l0 | ((ull)l1 << 32);
            }
        }
        // ---- stage Hs ----
        if (GATHER) {
            int cc = (tid & 15) << 2;
            #pragma unroll
            for (int b = 0; b < 8; b++) {
                int n = b * 16 + (tid >> 4);
                int node = base + n;
                if (node < rows) {
                    int beg = rp[n], end = rp[n + 1];
                    float4 acc = *(const float4*)(X + (size_t)node * D + cc);
                    float4 acc2 = make_float4(0.f, 0.f, 0.f, 0.f);
                    int e = beg;
                    for (; e + 3 < end; e += 4) {
                        int s0 = __ldg(&g_csr[e]),     s1 = __ldg(&g_csr[e + 1]);
                        int s2 = __ldg(&g_csr[e + 2]), s3 = __ldg(&g_csr[e + 3]);
                        float4 v0 = *(const float4*)(X + (size_t)s0 * D + cc);
                        float4 v1 = *(const float4*)(X + (size_t)s1 * D + cc);
                        float4 v2 = *(const float4*)(X + (size_t)s2 * D + cc);
                        float4 v3 = *(const float4*)(X + (size_t)s3 * D + cc);
                        acc.x  += v0.x + v1.x; acc.y  += v0.y + v1.y;
                        acc.z  += v0.z + v1.z; acc.w  += v0.w + v1.w;
                        acc2.x += v2.x + v3.x; acc2.y += v2.y + v3.y;
                        acc2.z += v2.z + v3.z; acc2.w += v2.w + v3.w;
                    }
                    for (; e < end; e++) {
                        int s0 = __ldg(&g_csr[e]);
                        float4 v0 = *(const float4*)(X + (size_t)s0 * D + cc);
                        acc.x += v0.x; acc.y += v0.y; acc.z += v0.z; acc.w += v0.w;
                    }
                    acc.x += acc2.x; acc.y += acc2.y; acc.z += acc2.z; acc.w += acc2.w;
                    *(float4*)(Hs + n * HS + cc) = acc;
                }
            }
        } else {
            const float* Xp = X + (size_t)ps * xStride;
            #pragma unroll
            for (int it = 0; it < RPB * 16 / 256; it++) {
                int i = it * 256 + tid;
                int r = i >> 4, cc = (i & 15) << 2;
                int row = base + r;
                if (row < rows) {
                    float4 v = *(const float4*)(Xp + (size_t)row * D + cc);
                    if (IN_BN) {
                        v.x = fmaxf(v.x * ssa[cc]   + ssb[cc],   0.f);
                        v.y = fmaxf(v.y * ssa[cc+1] + ssb[cc+1], 0.f);
                        v.z = fmaxf(v.z * ssa[cc+2] + ssb[cc+2], 0.f);
                        v.w = fmaxf(v.w * ssa[cc+3] + ssb[cc+3], 0.f);
                    }
                    *(float4*)(Hs + r * HS + cc) = v;
                }
            }
        }
        __syncthreads();

        // ---- MMA mainloop ----
        const float* ar0 = Hs + (w * 16 + g) * HS;
        const float* ar1 = ar0 + 8 * HS;
        #pragma unroll
        for (int ks = 0; ks < 8; ks++) {
            int kc = ks * 8 + t;
            float x00 = ar0[kc], x01 = ar0[kc + 4];
            float x10 = ar1[kc], x11 = ar1[kc + 4];
            // a0: (row g, k t) a1: (row g+8, k t) a2: (g, t+4) a3: (g+8, t+4)
            uint32_t ah0 = cvt_tf32(x00), ah1 = cvt_tf32(x10);
            uint32_t ah2 = cvt_tf32(x01), ah3 = cvt_tf32(x11);
            uint32_t al0 = cvt_tf32(x00 - __uint_as_float(ah0));
            uint32_t al1 = cvt_tf32(x10 - __uint_as_float(ah1));
            uint32_t al2 = cvt_tf32(x01 - __uint_as_float(ah2));
            uint32_t al3 = cvt_tf32(x11 - __uint_as_float(ah3));
            #pragma unroll
            for (int nt = 0; nt < 8; nt++) {
                ull bh = WBh[(ks * 8 + nt) * 32 + l];
                ull bl = WBl[(ks * 8 + nt) * 32 + l];
                uint32_t bh0 = (uint32_t)bh, bh1 = (uint32_t)(bh >> 32);
                uint32_t bl0 = (uint32_t)bl, bl1 = (uint32_t)(bl >> 32);
                mma_tf32(c[nt], ah0, ah1, ah2, ah3, bh0, bh1);
                mma_tf32(c[nt], al0, al1, al2, al3, bh0, bh1);
                mma_tf32(c[nt], ah0, ah1, ah2, ah3, bl0, bl1);
            }
        }
    }

    // ---- store: rows r0 = base + w*16 + g, r1 = r0 + 8; cols nt*8 + 2t ----
    int r0 = base + w * 16 + g, r1 = r0 + 8;
    bool v0 = (r0 < rows), v1 = (r1 < rows);
    #pragma unroll
    for (int nt = 0; nt < 8; nt++) {
        int col = nt * 8 + 2 * t;
        if (v0) {
            float2 o = make_float2(c[nt][0], c[nt][1]);
            if (OUT_RELU) { o.x = fmaxf(o.x, 0.f); o.y = fmaxf(o.y, 0.f); }
            *(float2*)(O + (size_t)r0 * D + col) = o;
        }
        if (v1) {
            float2 o = make_float2(c[nt][2], c[nt][3]);
            if (OUT_RELU) { o.x = fmaxf(o.x, 0.f); o.y = fmaxf(o.y, 0.f); }
            *(float2*)(O + (size_t)r1 * D + col) = o;
        }
    }

    if (STATS) {
        #pragma unroll
        for (int nt = 0; nt < 8; nt++) {
            float e0 = v0 ? c[nt][0] : 0.f, e1 = v0 ? c[nt][1] : 0.f;
            float e2 = v1 ? c[nt][2] : 0.f, e3 = v1 ? c[nt][3] : 0.f;
            float s0 = e0 + e2, s1 = e1 + e3;
            float q0 = e0 * e0 + e2 * e2, q1 = e1 * e1 + e3 * e3;
            #pragma unroll
            for (int off = 4; off < 32; off <<= 1) {
                s0 += __shfl_xor_sync(0xffffffff, s0, off);
                s1 += __shfl_xor_sync(0xffffffff, s1, off);
                q0 += __shfl_xor_sync(0xffffffff, q0, off);
                q1 += __shfl_xor_sync(0xffffffff, q1, off);
            }
            if (l < 4) {
                int col = nt * 8 + 2 * t;
                atomicAdd(&sbuf[col],         s0);
                atomicAdd(&sbuf[col + 1],     s1);
                atomicAdd(&sbuf[D + col],     q0);
                atomicAdd(&sbuf[D + col + 1], q1);
            }
        }
        __syncthreads();
        if (tid < 2 * D) atomicAdd(&statsOut[tid], sbuf[tid]);
    }
}

// segmented pool
__global__ void k_pool_seg(const float* __restrict__ XJ) {
    int t = blockIdx.x * 256 + threadIdx.x;
    int m = t >> 4;
    if (m >= NM) return;
    int c = (t & 15) << 2;
    int beg = g_molptr[m], end = g_molptr[m + 1];
    float4 acc = make_float4(0.f, 0.f, 0.f, 0.f);
    for (int n = beg; n < end; n++) {
        float4 v = *(const float4*)(XJ + (size_t)n * D + c);
        acc.x += v.x; acc.y += v.y; acc.z += v.z; acc.w += v.w;
    }
    *(float4*)(g_G + (size_t)m * D + c) = acc;
}

// out = relu(TG*bn) @ (W2 @ oW) + (b2 @ oW + ob)
__global__ __launch_bounds__(256) void k_final(
    const float* __restrict__ W2, const float* __restrict__ oW,
    const float* __restrict__ b2, const float* __restrict__ ob,
    const float* __restrict__ gg, const float* __restrict__ be,
    float* __restrict__ out, int rows)
{
    __shared__ float Ws[D * NO];
    __shared__ float bcs[NO], sa[D], sb[D];
    int tid = threadIdx.x;
    const float* statsIn = g_stats + 3 * 2 * D;
    for (int i = tid; i < D * NO; i += 256) {
        int k = i / NO, o = i % NO;
        float sum = 0.f;
        for (int j = 0; j < D; j++) sum += W2[k * D + j] * oW[j * NO + o];
        Ws[i] = sum;
    }
    if (tid < NO) {
        float sum = ob[tid];
        for (int j = 0; j < D; j++) sum += b2[j] * oW[j * NO + tid];
        bcs[tid] = sum;
    }
    if (tid < D) {
        float mu  = statsIn[tid] * (1.0f / NM);
        float var = statsIn[D + tid] * (1.0f / NM) - mu * mu;
        float rs  = rsqrtf(var + BN_EPS);
        float a   = rs * gg[tid];
        sa[tid] = a; sb[tid] = be[tid] - mu * a;
    }
    __syncthreads();
    int row = blockIdx.x * 256 + tid;
    if (row >= rows) return;
    float acc[NO];
    #pragma unroll
    for (int o = 0; o < NO; o++) acc[o] = bcs[o];
    const float* tr = g_TG + (size_t)row * D;
    for (int k = 0; k < D; k++) {
        float h = fmaxf(tr[k] * sa[k] + sb[k], 0.f);
        #pragma unroll
        for (int o = 0; o < NO; o++) acc[o] += h * Ws[k * NO + o];
    }
    float* orow = out + (size_t)row * NO;
    #pragma unroll
    for (int o = 0; o < NO; o++) orow[o] = acc[o];
}

// ---------------- host ----------------
extern "C" void kernel_launch(void* const* d_in, const int* in_sizes, int n_in,
                              void* d_out, int out_size)
{
    const int*   atom_ids = (const int*)  d_in[0];
    const int*   edge     = (const int*)  d_in[1];
    const int*   mol_ids  = (const int*)  d_in[2];
    const float* emb_W    = (const float*)d_in[3];
    const float* gin_W1   = (const float*)d_in[4];
    const float* gin_b1   = (const float*)d_in[5];
    const float* gin_g1   = (const float*)d_in[6];
    const float* gin_be1  = (const float*)d_in[7];
    const float* gin_W2   = (const float*)d_in[8];
    const float* gin_b2   = (const float*)d_in[9];
    const float* jk_W     = (const float*)d_in[10];
    const float* jk_b     = (const float*)d_in[11];
    const float* ffn_W1   = (const float*)d_in[12];
    const float* ffn_b1   = (const float*)d_in[13];
    const float* ffn_g    = (const float*)d_in[14];
    const float* ffn_be   = (const float*)d_in[15];
    const float* ffn_W2   = (const float*)d_in[16];
    const float* ffn_b2   = (const float*)d_in[17];
    const float* out_W    = (const float*)d_in[18];
    const float* out_b    = (const float*)d_in[19];
    float* out = (float*)d_out;

    const int* src = edge;
    const int* dst = edge + NE;

    float *X0, *T, *XS, *G, *TG, *stats;
    cudaGetSymbolAddress((void**)&X0,    g_X0);
    cudaGetSymbolAddress((void**)&T,     g_T);
    cudaGetSymbolAddress((void**)&XS,    g_XS);
    cudaGetSymbolAddress((void**)&G,     g_G);
    cudaGetSymbolAddress((void**)&TG,    g_TG);
    cudaGetSymbolAddress((void**)&stats, g_stats);

    cudaFuncSetAttribute(k_gemm<1,0,0,1,1>, cudaFuncAttributeMaxDynamicSharedMemorySize, SMEM_G);
    cudaFuncSetAttribute(k_gemm<0,1,1,0,1>, cudaFuncAttributeMaxDynamicSharedMemorySize, SMEM_G);
    cudaFuncSetAttribute(k_gemm<0,0,0,0,NL>, cudaFuncAttributeMaxDynamicSharedMemorySize, SMEM_G);
    cudaFuncSetAttribute(k_gemm<0,0,0,1,1>, cudaFuncAttributeMaxDynamicSharedMemorySize, SMEM_G);

    k_init<<<(NN + 255)/256, 256>>>();
    k_embed<<<(NN*16 + 255)/256, 256>>>(atom_ids, emb_W);
    {
        void* args[] = { (void*)&src, (void*)&dst };
        cudaLaunchCooperativeKernel((void*)k_csr_coop, dim3(COOP_BLOCKS), dim3(256),
                                    args, 0, (cudaStream_t)0);
    }

    const int GRID = (NN + RPB - 1) / RPB;
    for (int l = 0; l < NL; l++) {
        const float* xin = (l == 0) ? X0 : XS + (size_t)(l-1) * NN * D;
        float* slot = stats + (size_t)l * 2 * D;
        // gemm1: gather + GEMM + stats -> T
        k_gemm<1,0,0,1,1><<<GRID, 256, SMEM_G>>>(
            xin, gin_W1 + (size_t)l*D*D, gin_b1 + l*D, T, NN,
            nullptr, slot, nullptr, nullptr, 0.f, 0, 0);
        // gemm2: BN+relu stage + GEMM + relu -> XS[l]
        k_gemm<0,1,1,0,1><<<GRID, 256, SMEM_G>>>(
            T, gin_W2 + (size_t)l*D*D, gin_b2 + l*D, XS + (size_t)l*NN*D, NN,
            slot, nullptr, gin_g1 + l*D, gin_be1 + l*D, 1.0f / NN, 0, 0);
    }

    k_molptr<<<(NN + 255)/256, 256>>>(mol_ids);
    // JK: 3-pass accumulate -> X0
    k_gemm<0,0,0,0,NL><<<GRID, 256, SMEM_G>>>(
        XS, jk_W, jk_b, X0, NN,
        nullptr, nullptr, nullptr, nullptr, 0.f, (size_t)NN * D, (size_t)D * D);

    k_pool_seg<<<(NM*16 + 255)/256, 256>>>(X0);

    float* slot3 = stats + 3 * 2 * D;
    k_gemm<0,0,0,1,1><<<(NM + RPB - 1)/RPB, 256, SMEM_G>>>(
        G, ffn_W1, ffn_b1, TG, NM,
        nullptr, slot3, nullptr, nullptr, 0.f, 0, 0);

    k_final<<<(NM + 255)/256, 256>>>(ffn_W2, out_W, ffn_b2, out_b,
                                     ffn_g, ffn_be, out, NM);
}

// round 13
// speedup vs baseline: 1.4230x; 1.0192x over previous
#include <cuda_runtime.h>
#include <cooperative_groups.h>
namespace cg = cooperative_groups;

#define NN 100000
#define NE 1200000
#define D 64
#define NL 3
#define NM 5000
#define NO 24
#define BN_EPS 1e-5f
#define NB_SCAN ((NN + 1023) / 1024)
#define HS 68          // smem row stride (floats): 272B, float4-aligned, conflict-free
#define RPB 128        // rows per block
#define COOP_BLOCKS 592
#define SMEM_G (RPB * HS * 4 + 2 * 2048 * 8)   // Hs + WBh + WBl = 67584 B

typedef unsigned long long ull;

// ---------------- scratch ----------------
__device__ __align__(128) float g_X0 [NN * D];
__device__ __align__(128) float g_T  [NN * D];
__device__ __align__(128) float g_XS [NL * NN * D];
__device__ __align__(128) float g_G  [NM * D];
__device__ __align__(128) float g_TG [NM * D];
__device__ __align__(128) float g_stats[4 * 2 * D];
__device__ __align__(128) int g_deg   [NN];
__device__ __align__(128) int g_cur   [NN];
__device__ __align__(128) int g_rowptr[NN + 1];
__device__ __align__(128) int g_csr   [NE];
__device__ __align__(128) int g_bsum  [NB_SCAN];
__device__ __align__(128) int g_boff  [NB_SCAN];
__device__ __align__(128) int g_molptr[NM + 1];

// ---------------- helpers ----------------
__device__ __forceinline__ uint32_t cvt_tf32(float x) {
    uint32_t r; asm("cvt.rna.tf32.f32 %0, %1;" : "=r"(r) : "f"(x)); return r;
}
__device__ __forceinline__ void mma_tf32(float* c, uint32_t a0, uint32_t a1,
                                         uint32_t a2, uint32_t a3,
                                         uint32_t b0, uint32_t b1) {
    asm volatile(
        "mma.sync.aligned.m16n8k8.row.col.f32.tf32.tf32.f32 "
        "{%0,%1,%2,%3},{%4,%5,%6,%7},{%8,%9},{%0,%1,%2,%3};"
        : "+f"(c[0]), "+f"(c[1]), "+f"(c[2]), "+f"(c[3])
        : "r"(a0), "r"(a1), "r"(a2), "r"(a3), "r"(b0), "r"(b1));
}

// ---------------- init ----------------
__global__ void k_init() {
    int t = blockIdx.x * blockDim.x + threadIdx.x;
    if (t < NN) { g_deg[t] = 0; g_cur[t] = 0; }
    if (t < 4 * 2 * D) g_stats[t] = 0.f;
}

__global__ void k_embed(const int* __restrict__ atom_ids, const float* __restrict__ embW) {
    int t = blockIdx.x * blockDim.x + threadIdx.x;
    if (t >= NN * 16) return;
    int n = t >> 4, c = (t & 15) << 2;
    int a = __ldg(atom_ids + n);
    *(float4*)(g_X0 + (size_t)n * D + c) = *(const float4*)(embW + (size_t)a * D + c);
}

// ---------------- cooperative CSR build -----------------
__global__ void k_csr_coop(const int* __restrict__ src, const int* __restrict__ dst) {
    cg::grid_group grid = cg::this_grid();
    int tid = threadIdx.x, bid = blockIdx.x;
    int gt = bid * 256 + tid, gs = gridDim.x * 256;

    for (int e = gt; e < NE; e += gs) atomicAdd(&g_deg[__ldg(dst + e)], 1);
    grid.sync();

    __shared__ int sh[256];
    if (bid < NB_SCAN) {
        int base = bid * 1024;
        int loc[4]; int s = 0;
        #pragma unroll
        for (int j = 0; j < 4; j++) {
            int i = base + tid * 4 + j;
            int v = (i < NN) ? g_deg[i] : 0;
            s += v; loc[j] = s;
        }
        int excl_in = s;
        sh[tid] = excl_in; __syncthreads();
        for (int off = 1; off < 256; off <<= 1) {
            int t2 = (tid >= off) ? sh[tid - off] : 0;
            __syncthreads();
            sh[tid] += t2;
            __syncthreads();
        }
        int pre = sh[tid] - excl_in;
        #pragma unroll
        for (int j = 0; j < 4; j++) {
            int i = base + tid * 4 + j;
            if (i < NN) g_rowptr[i + 1] = pre + loc[j];
        }
        if (tid == 255) g_bsum[bid] = sh[255];
    }
    grid.sync();

    if (bid == 0 && tid < 32) {
        int carry = 0;
        for (int b = 0; b < NB_SCAN; b += 32) {
            int idx = b + tid;
            int v = (idx < NB_SCAN) ? g_bsum[idx] : 0;
            int x = v;
            #pragma unroll
            for (int off = 1; off < 32; off <<= 1) {
                int y = __shfl_up_sync(0xffffffff, x, off);
                if (tid >= off) x += y;
            }
            if (idx < NB_SCAN) g_boff[idx] = carry + x - v;
            carry += __shfl_sync(0xffffffff, x, 31);
        }
    }
    grid.sync();

    if (gt == 0) g_rowptr[0] = 0;
    for (int i = gt; i < NN; i += gs) g_rowptr[i + 1] += g_boff[i >> 10];
    grid.sync();

    for (int e = gt; e < NE; e += gs) {
        int d = __ldg(dst + e);
        int pos = g_rowptr[d] + atomicAdd(&g_cur[d], 1);
        g_csr[pos] = __ldg(src + e);
    }
}

__global__ void k_molptr(const int* __restrict__ mol) {
    int t = blockIdx.x * blockDim.x + threadIdx.x;
    if (t >= NN) return;
    int m1 = __ldg(mol + t);
    int m0 = (t == 0) ? -1 : __ldg(mol + t - 1);
    for (int m = m0 + 1; m <= m1; m++) g_molptr[m] = t;
    if (t == NN - 1)
        for (int m = m1 + 1; m <= NM; m++) g_molptr[m] = NN;
}

// ============================================================================
// Unified GEMM kernel, tensor-core (mma.sync tf32, 3xTF32) inner loop.
// 128 rows/block, 8 warps; warp w owns rows [w*16, w*16+16) x all 64 cols.
// Gather phase: software-pipelined csr-index prefetch.
// ============================================================================
template<int GATHER, int IN_BN, int OUT_RELU, int STATS, int NPASS>
__global__ __launch_bounds__(256) void k_gemm(
    const float* __restrict__ X, const float* __restrict__ W,
    const float* __restrict__ bias, float* __restrict__ O, int rows,
    const float* __restrict__ statsIn, float* __restrict__ statsOut,
    const float* __restrict__ gg, const float* __restrict__ be, float inv_n,
    size_t xStride, size_t wStride)
{
    extern __shared__ __align__(16) float dsm[];
    float* Hs = dsm;                         // RPB*HS floats
    ull*   WBh = (ull*)(dsm + RPB * HS);     // 2048 ull (fragment-order W hi)
    ull*   WBl = WBh + 2048;                 // 2048 ull (fragment-order W lo)
    __shared__ float ssa[D], ssb[D];
    __shared__ float sbuf[2 * D];
    __shared__ int   rp[RPB + 1];
    int tid = threadIdx.x;
    int base = blockIdx.x * RPB;
    int w = tid >> 5, l = tid & 31;
    int g = l >> 2, t = l & 3;

    if (IN_BN && tid < D) {
        float mu  = statsIn[tid] * inv_n;
        float var = statsIn[D + tid] * inv_n - mu * mu;
        float rs  = rsqrtf(var + BN_EPS);
        float a   = rs * gg[tid];
        ssa[tid] = a; ssb[tid] = be[tid] - mu * a;
    }
    if (STATS && tid < 2 * D) sbuf[tid] = 0.f;
    if (GATHER && tid <= RPB) {
        int node = base + tid;
        rp[tid] = (node <= rows) ? __ldg(&g_rowptr[node]) : 0;
    }

    // C fragments: 8 n-tiles x 4 regs. Init with bias (both row groups same col).
    float c[8][4];
    #pragma unroll
    for (int nt = 0; nt < 8; nt++) {
        float2 b2 = *(const float2*)(bias + nt * 8 + 2 * t);
        c[nt][0] = b2.x; c[nt][1] = b2.y; c[nt][2] = b2.x; c[nt][3] = b2.y;
    }

    for (int ps = 0; ps < NPASS; ps++) {
        __syncthreads();
        // ---- stage W into fragment-order hi/lo arrays ----
        {
            const float* Wp = W + (size_t)ps * wStride;
            for (int i = tid; i < 2048; i += 256) {
                int ent = i >> 5, ll = i & 31;
                int ks = ent >> 3, nt = ent & 7;
                int k0 = ks * 8 + (ll & 3), n = nt * 8 + (ll >> 2);
                float w0 = __ldg(&Wp[k0 * D + n]);
                float w1 = __ldg(&Wp[(k0 + 4) * D + n]);
                uint32_t h0 = cvt_tf32(w0), h1 = cvt_tf32(w1);
                uint32_t l0 = cvt_tf32(w0 - __uint_as_float(h0));
                uint32_t l1 = cvt_tf32(w1 - __uint_as_float(h1));
                WBh[i] = (ull)h0 | ((ull)h1 << 32);
                WBl[i] = (ull)l0 | ((ull)l1 << 32);
            }
        }
        // ---- stage Hs ----
        if (GATHER) {
            int cc = (tid & 15) << 2;
            #pragma unroll
            for (int b = 0; b < 8; b++) {
                int n = b * 16 + (tid >> 4);
                int node = base + n;
                if (node < rows) {
                    int beg = rp[n], end = rp[n + 1];
                    float4 acc = *(const float4*)(X + (size_t)node * D + cc);
                    int e = beg;
                    int i0, i1, i2, i3;
                    bool have = (e + 3 < end);
                    if (have) {
                        i0 = __ldg(&g_csr[e]);     i1 = __ldg(&g_csr[e + 1]);
                        i2 = __ldg(&g_csr[e + 2]); i3 = __ldg(&g_csr[e + 3]);
                    }
                    while (have) {
                        int en = e + 4;
                        bool hn = (en + 3 < end);
                        int j0, j1, j2, j3;
                        if (hn) {   // prefetch next batch's indices first
                            j0 = __ldg(&g_csr[en]);     j1 = __ldg(&g_csr[en + 1]);
                            j2 = __ldg(&g_csr[en + 2]); j3 = __ldg(&g_csr[en + 3]);
                        }
                        float4 v0 = *(const float4*)(X + (size_t)i0 * D + cc);
                        float4 v1 = *(const float4*)(X + (size_t)i1 * D + cc);
                        float4 v2 = *(const float4*)(X + (size_t)i2 * D + cc);
                        float4 v3 = *(const float4*)(X + (size_t)i3 * D + cc);
                        acc.x += (v0.x + v1.x) + (v2.x + v3.x);
                        acc.y += (v0.y + v1.y) + (v2.y + v3.y);
                        acc.z += (v0.z + v1.z) + (v2.z + v3.z);
                        acc.w += (v0.w + v1.w) + (v2.w + v3.w);
                        e = en; have = hn;
                        i0 = j0; i1 = j1; i2 = j2; i3 = j3;
                    }
                    for (; e < end; e++) {
                        int s0 = __ldg(&g_csr[e]);
                        float4 v0 = *(const float4*)(X + (size_t)s0 * D + cc);
                        acc.x += v0.x; acc.y += v0.y; acc.z += v0.z; acc.w += v0.w;
                    }
                    *(float4*)(Hs + n * HS + cc) = acc;
                }
            }
        } else {
            const float* Xp = X + (size_t)ps * xStride;
            #pragma unroll
            for (int it = 0; it < RPB * 16 / 256; it++) {
                int i = it * 256 + tid;
                int r = i >> 4, cc = (i & 15) << 2;
                int row = base + r;
                if (row < rows) {
                    float4 v = *(const float4*)(Xp + (size_t)row * D + cc);
                    if (IN_BN) {
                        v.x = fmaxf(v.x * ssa[cc]   + ssb[cc],   0.f);
                        v.y = fmaxf(v.y * ssa[cc+1] + ssb[cc+1], 0.f);
                        v.z = fmaxf(v.z * ssa[cc+2] + ssb[cc+2], 0.f);
                        v.w = fmaxf(v.w * ssa[cc+3] + ssb[cc+3], 0.f);
                    }
                    *(float4*)(Hs + r * HS + cc) = v;
                }
            }
        }
        __syncthreads();

        // ---- MMA mainloop ----
        const float* ar0 = Hs + (w * 16 + g) * HS;
        const float* ar1 = ar0 + 8 * HS;
        #pragma unroll
        for (int ks = 0; ks < 8; ks++) {
            int kc = ks * 8 + t;
            float x00 = ar0[kc], x01 = ar0[kc + 4];
            float x10 = ar1[kc], x11 = ar1[kc + 4];
            uint32_t ah0 = cvt_tf32(x00), ah1 = cvt_tf32(x10);
            uint32_t ah2 = cvt_tf32(x01), ah3 = cvt_tf32(x11);
            uint32_t al0 = cvt_tf32(x00 - __uint_as_float(ah0));
            uint32_t al1 = cvt_tf32(x10 - __uint_as_float(ah1));
            uint32_t al2 = cvt_tf32(x01 - __uint_as_float(ah2));
            uint32_t al3 = cvt_tf32(x11 - __uint_as_float(ah3));
            #pragma unroll
            for (int nt = 0; nt < 8; nt++) {
                ull bh = WBh[(ks * 8 + nt) * 32 + l];
                ull bl = WBl[(ks * 8 + nt) * 32 + l];
                uint32_t bh0 = (uint32_t)bh, bh1 = (uint32_t)(bh >> 32);
                uint32_t bl0 = (uint32_t)bl, bl1 = (uint32_t)(bl >> 32);
                mma_tf32(c[nt], ah0, ah1, ah2, ah3, bh0, bh1);
                mma_tf32(c[nt], al0, al1, al2, al3, bh0, bh1);
                mma_tf32(c[nt], ah0, ah1, ah2, ah3, bl0, bl1);
            }
        }
    }

    // ---- store: rows r0 = base + w*16 + g, r1 = r0 + 8; cols nt*8 + 2t ----
    int r0 = base + w * 16 + g, r1 = r0 + 8;
    bool v0 = (r0 < rows), v1 = (r1 < rows);
    #pragma unroll
    for (int nt = 0; nt < 8; nt++) {
        int col = nt * 8 + 2 * t;
        if (v0) {
            float2 o = make_float2(c[nt][0], c[nt][1]);
            if (OUT_RELU) { o.x = fmaxf(o.x, 0.f); o.y = fmaxf(o.y, 0.f); }
            *(float2*)(O + (size_t)r0 * D + col) = o;
        }
        if (v1) {
            float2 o = make_float2(c[nt][2], c[nt][3]);
            if (OUT_RELU) { o.x = fmaxf(o.x, 0.f); o.y = fmaxf(o.y, 0.f); }
            *(float2*)(O + (size_t)r1 * D + col) = o;
        }
    }

    if (STATS) {
        #pragma unroll
        for (int nt = 0; nt < 8; nt++) {
            float e0 = v0 ? c[nt][0] : 0.f, e1 = v0 ? c[nt][1] : 0.f;
            float e2 = v1 ? c[nt][2] : 0.f, e3 = v1 ? c[nt][3] : 0.f;
            float s0 = e0 + e2, s1 = e1 + e3;
            float q0 = e0 * e0 + e2 * e2, q1 = e1 * e1 + e3 * e3;
            #pragma unroll
            for (int off = 4; off < 32; off <<= 1) {
                s0 += __shfl_xor_sync(0xffffffff, s0, off);
                s1 += __shfl_xor_sync(0xffffffff, s1, off);
                q0 += __shfl_xor_sync(0xffffffff, q0, off);
                q1 += __shfl_xor_sync(0xffffffff, q1, off);
            }
            if (l < 4) {
                int col = nt * 8 + 2 * t;
                atomicAdd(&sbuf[col],         s0);
                atomicAdd(&sbuf[col + 1],     s1);
                atomicAdd(&sbuf[D + col],     q0);
                atomicAdd(&sbuf[D + col + 1], q1);
            }
        }
        __syncthreads();
        if (tid < 2 * D) atomicAdd(&statsOut[tid], sbuf[tid]);
    }
}

// segmented pool
__global__ void k_pool_seg(const float* __restrict__ XJ) {
    int t = blockIdx.x * 256 + threadIdx.x;
    int m = t >> 4;
    if (m >= NM) return;
    int c = (t & 15) << 2;
    int beg = g_molptr[m], end = g_molptr[m + 1];
    float4 acc = make_float4(0.f, 0.f, 0.f, 0.f);
    for (int n = beg; n < end; n++) {
        float4 v = *(const float4*)(XJ + (size_t)n * D + c);
        acc.x += v.x; acc.y += v.y; acc.z += v.z; acc.w += v.w;
    }
    *(float4*)(g_G + (size_t)m * D + c) = acc;
}

// out = relu(TG*bn) @ (W2 @ oW) + (b2 @ oW + ob)
__global__ __launch_bounds__(256) void k_final(
    const float* __restrict__ W2, const float* __restrict__ oW,
    const float* __restrict__ b2, const float* __restrict__ ob,
    const float* __restrict__ gg, const float* __restrict__ be,
    float* __restrict__ out, int rows)
{
    __shared__ float Ws[D * NO];
    __shared__ float bcs[NO], sa[D], sb[D];
    int tid = threadIdx.x;
    const float* statsIn = g_stats + 3 * 2 * D;
    for (int i = tid; i < D * NO; i += 256) {
        int k = i / NO, o = i % NO;
        float sum = 0.f;
        for (int j = 0; j < D; j++) sum += W2[k * D + j] * oW[j * NO + o];
        Ws[i] = sum;
    }
    if (tid < NO) {
        float sum = ob[tid];
        for (int j = 0; j < D; j++) sum += b2[j] * oW[j * NO + tid];
        bcs[tid] = sum;
    }
    if (tid < D) {
        float mu  = statsIn[tid] * (1.0f / NM);
        float var = statsIn[D + tid] * (1.0f / NM) - mu * mu;
        float rs  = rsqrtf(var + BN_EPS);
        float a   = rs * gg[tid];
        sa[tid] = a; sb[tid] = be[tid] - mu * a;
    }
    __syncthreads();
    int row = blockIdx.x * 256 + tid;
    if (row >= rows) return;
    float acc[NO];
    #pragma unroll
    for (int o = 0; o < NO; o++) acc[o] = bcs[o];
    const float* tr = g_TG + (size_t)row * D;
    for (int k = 0; k < D; k++) {
        float h = fmaxf(tr[k] * sa[k] + sb[k], 0.f);
        #pragma unroll
        for (int o = 0; o < NO; o++) acc[o] += h * Ws[k * NO + o];
    }
    float* orow = out + (size_t)row * NO;
    #pragma unroll
    for (int o = 0; o < NO; o++) orow[o] = acc[o];
}

// ---------------- host ----------------
extern "C" void kernel_launch(void* const* d_in, const int* in_sizes, int n_in,
                              void* d_out, int out_size)
{
    const int*   atom_ids = (const int*)  d_in[0];
    const int*   edge     = (const int*)  d_in[1];
    const int*   mol_ids  = (const int*)  d_in[2];
    const float* emb_W    = (const float*)d_in[3];
    const float* gin_W1   = (const float*)d_in[4];
    const float* gin_b1   = (const float*)d_in[5];
    const float* gin_g1   = (const float*)d_in[6];
    const float* gin_be1  = (const float*)d_in[7];
    const float* gin_W2   = (const float*)d_in[8];
    const float* gin_b2   = (const float*)d_in[9];
    const float* jk_W     = (const float*)d_in[10];
    const float* jk_b     = (const float*)d_in[11];
    const float* ffn_W1   = (const float*)d_in[12];
    const float* ffn_b1   = (const float*)d_in[13];
    const float* ffn_g    = (const float*)d_in[14];
    const float* ffn_be   = (const float*)d_in[15];
    const float* ffn_W2   = (const float*)d_in[16];
    const float* ffn_b2   = (const float*)d_in[17];
    const float* out_W    = (const float*)d_in[18];
    const float* out_b    = (const float*)d_in[19];
    float* out = (float*)d_out;

    const int* src = edge;
    const int* dst = edge + NE;

    float *X0, *T, *XS, *G, *TG, *stats;
    cudaGetSymbolAddress((void**)&X0,    g_X0);
    cudaGetSymbolAddress((void**)&T,     g_T);
    cudaGetSymbolAddress((void**)&XS,    g_XS);
    cudaGetSymbolAddress((void**)&G,     g_G);
    cudaGetSymbolAddress((void**)&TG,    g_TG);
    cudaGetSymbolAddress((void**)&stats, g_stats);

    cudaFuncSetAttribute(k_gemm<1,0,0,1,1>, cudaFuncAttributeMaxDynamicSharedMemorySize, SMEM_G);
    cudaFuncSetAttribute(k_gemm<0,1,1,0,1>, cudaFuncAttributeMaxDynamicSharedMemorySize, SMEM_G);
    cudaFuncSetAttribute(k_gemm<0,0,0,0,NL>, cudaFuncAttributeMaxDynamicSharedMemorySize, SMEM_G);
    cudaFuncSetAttribute(k_gemm<0,0,0,1,1>, cudaFuncAttributeMaxDynamicSharedMemorySize, SMEM_G);

    k_init<<<(NN + 255)/256, 256>>>();
    k_embed<<<(NN*16 + 255)/256, 256>>>(atom_ids, emb_W);
    {
        void* args[] = { (void*)&src, (void*)&dst };
        cudaLaunchCooperativeKernel((void*)k_csr_coop, dim3(COOP_BLOCKS), dim3(256),
                                    args, 0, (cudaStream_t)0);
    }

    const int GRID = (NN + RPB - 1) / RPB;
    for (int l = 0; l < NL; l++) {
        const float* xin = (l == 0) ? X0 : XS + (size_t)(l-1) * NN * D;
        float* slot = stats + (size_t)l * 2 * D;
        // gemm1: gather + GEMM + stats -> T
        k_gemm<1,0,0,1,1><<<GRID, 256, SMEM_G>>>(
            xin, gin_W1 + (size_t)l*D*D, gin_b1 + l*D, T, NN,
            nullptr, slot, nullptr, nullptr, 0.f, 0, 0);
        // gemm2: BN+relu stage + GEMM + relu -> XS[l]
        k_gemm<0,1,1,0,1><<<GRID, 256, SMEM_G>>>(
            T, gin_W2 + (size_t)l*D*D, gin_b2 + l*D, XS + (size_t)l*NN*D, NN,
            slot, nullptr, gin_g1 + l*D, gin_be1 + l*D, 1.0f / NN, 0, 0);
    }

    k_molptr<<<(NN + 255)/256, 256>>>(mol_ids);
    // JK: 3-pass accumulate -> X0
    k_gemm<0,0,0,0,NL><<<GRID, 256, SMEM_G>>>(
        XS, jk_W, jk_b, X0, NN,
        nullptr, nullptr, nullptr, nullptr, 0.f, (size_t)NN * D, (size_t)D * D);

    k_pool_seg<<<(NM*16 + 255)/256, 256>>>(X0);

    float* slot3 = stats + 3 * 2 * D;
    k_gemm<0,0,0,1,1><<<(NM + RPB - 1)/RPB, 256, SMEM_G>>>(
        G, ffn_W1, ffn_b1, TG, NM,
        nullptr, slot3, nullptr, nullptr, 0.f, 0, 0);

    k_final<<<(NM + 255)/256, 256>>>(ffn_W2, out_W, ffn_b2, out_b,
                                     ffn_g, ffn_be, out, NM);
}

// round 14
// speedup vs baseline: 1.4440x; 1.0148x over previous
#include <cuda_runtime.h>
#include <cooperative_groups.h>
namespace cg = cooperative_groups;

#define NN 100000
#define NE 1200000
#define D 64
#define NL 3
#define NM 5000
#define NO 24
#define BN_EPS 1e-5f
#define NB_SCAN ((NN + 1023) / 1024)
#define HS 68          // smem row stride (floats): 272B, float4-aligned, conflict-free
#define RPB 128        // rows per block
#define COOP_BLOCKS 592
#define SMEM_WB (2 * 2048 * 8)                   // 32768 B (W fragments hi+lo)
#define SMEM_GA (RPB * HS * 4 + SMEM_WB)         // 67584 B (gather path)

typedef unsigned long long ull;

// ---------------- scratch ----------------
__device__ __align__(128) float g_X0 [NN * D];
__device__ __align__(128) float g_T  [NN * D];
__device__ __align__(128) float g_XS [NL * NN * D];
__device__ __align__(128) float g_G  [NM * D];
__device__ __align__(128) float g_TG [NM * D];
__device__ __align__(128) float g_stats[4 * 2 * D];
__device__ __align__(128) int g_deg   [NN];
__device__ __align__(128) int g_cur   [NN];
__device__ __align__(128) int g_rowptr[NN + 1];
__device__ __align__(128) int g_csr   [NE];
__device__ __align__(128) int g_bsum  [NB_SCAN];
__device__ __align__(128) int g_boff  [NB_SCAN];
__device__ __align__(128) int g_molptr[NM + 1];

// ---------------- helpers ----------------
__device__ __forceinline__ uint32_t cvt_tf32(float x) {
    uint32_t r; asm("cvt.rna.tf32.f32 %0, %1;" : "=r"(r) : "f"(x)); return r;
}
__device__ __forceinline__ void mma_tf32(float* c, uint32_t a0, uint32_t a1,
                                         uint32_t a2, uint32_t a3,
                                         uint32_t b0, uint32_t b1) {
    asm volatile(
        "mma.sync.aligned.m16n8k8.row.col.f32.tf32.tf32.f32 "
        "{%0,%1,%2,%3},{%4,%5,%6,%7},{%8,%9},{%0,%1,%2,%3};"
        : "+f"(c[0]), "+f"(c[1]), "+f"(c[2]), "+f"(c[3])
        : "r"(a0), "r"(a1), "r"(a2), "r"(a3), "r"(b0), "r"(b1));
}

// ---------------- init ----------------
__global__ void k_init() {
    int t = blockIdx.x * blockDim.x + threadIdx.x;
    if (t < NN) { g_deg[t] = 0; g_cur[t] = 0; }
    if (t < 4 * 2 * D) g_stats[t] = 0.f;
}

__global__ void k_embed(const int* __restrict__ atom_ids, const float* __restrict__ embW) {
    int t = blockIdx.x * blockDim.x + threadIdx.x;
    if (t >= NN * 16) return;
    int n = t >> 4, c = (t & 15) << 2;
    int a = __ldg(atom_ids + n);
    *(float4*)(g_X0 + (size_t)n * D + c) = *(const float4*)(embW + (size_t)a * D + c);
}

// ---------------- cooperative CSR build -----------------
__global__ void k_csr_coop(const int* __restrict__ src, const int* __restrict__ dst) {
    cg::grid_group grid = cg::this_grid();
    int tid = threadIdx.x, bid = blockIdx.x;
    int gt = bid * 256 + tid, gs = gridDim.x * 256;

    for (int e = gt; e < NE; e += gs) atomicAdd(&g_deg[__ldg(dst + e)], 1);
    grid.sync();

    __shared__ int sh[256];
    if (bid < NB_SCAN) {
        int base = bid * 1024;
        int loc[4]; int s = 0;
        #pragma unroll
        for (int j = 0; j < 4; j++) {
            int i = base + tid * 4 + j;
            int v = (i < NN) ? g_deg[i] : 0;
            s += v; loc[j] = s;
        }
        int excl_in = s;
        sh[tid] = excl_in; __syncthreads();
        for (int off = 1; off < 256; off <<= 1) {
            int t2 = (tid >= off) ? sh[tid - off] : 0;
            __syncthreads();
            sh[tid] += t2;
            __syncthreads();
        }
        int pre = sh[tid] - excl_in;
        #pragma unroll
        for (int j = 0; j < 4; j++) {
            int i = base + tid * 4 + j;
            if (i < NN) g_rowptr[i + 1] = pre + loc[j];
        }
        if (tid == 255) g_bsum[bid] = sh[255];
    }
    grid.sync();

    if (bid == 0 && tid < 32) {
        int carry = 0;
        for (int b = 0; b < NB_SCAN; b += 32) {
            int idx = b + tid;
            int v = (idx < NB_SCAN) ? g_bsum[idx] : 0;
            int x = v;
            #pragma unroll
            for (int off = 1; off < 32; off <<= 1) {
                int y = __shfl_up_sync(0xffffffff, x, off);
                if (tid >= off) x += y;
            }
            if (idx < NB_SCAN) g_boff[idx] = carry + x - v;
            carry += __shfl_sync(0xffffffff, x, 31);
        }
    }
    grid.sync();

    if (gt == 0) g_rowptr[0] = 0;
    for (int i = gt; i < NN; i += gs) g_rowptr[i + 1] += g_boff[i >> 10];
    grid.sync();

    for (int e = gt; e < NE; e += gs) {
        int d = __ldg(dst + e);
        int pos = g_rowptr[d] + atomicAdd(&g_cur[d], 1);
        g_csr[pos] = __ldg(src + e);
    }
}

__global__ void k_molptr(const int* __restrict__ mol) {
    int t = blockIdx.x * blockDim.x + threadIdx.x;
    if (t >= NN) return;
    int m1 = __ldg(mol + t);
    int m0 = (t == 0) ? -1 : __ldg(mol + t - 1);
    for (int m = m0 + 1; m <= m1; m++) g_molptr[m] = t;
    if (t == NN - 1)
        for (int m = m1 + 1; m <= NM; m++) g_molptr[m] = NN;
}

// ============================================================================
// Unified GEMM kernel (mma.sync tf32, 3xTF32).
// GATHER=1: neighbor-sum staged in smem Hs (as before).
// GATHER=0: A-fragments loaded DIRECTLY from global (no smem staging, 32KB smem
//           -> 6 blocks/SM), BN applied inline.
// ============================================================================
template<int GATHER, int IN_BN, int OUT_RELU, int STATS, int NPASS>
__global__ __launch_bounds__(256) void k_gemm(
    const float* __restrict__ X, const float* __restrict__ W,
    const float* __restrict__ bias, float* __restrict__ O, int rows,
    const float* __restrict__ statsIn, float* __restrict__ statsOut,
    const float* __restrict__ gg, const float* __restrict__ be, float inv_n,
    size_t xStride, size_t wStride)
{
    extern __shared__ __align__(16) float dsm[];
    float* Hs  = dsm;                                        // gather path only
    ull*   WBh = (ull*)(GATHER ? (dsm + RPB * HS) : dsm);    // 2048 ull
    ull*   WBl = WBh + 2048;                                 // 2048 ull
    __shared__ float ssa[D], ssb[D];
    __shared__ float sbuf[2 * D];
    __shared__ int   rp[RPB + 1];
    int tid = threadIdx.x;
    int base = blockIdx.x * RPB;
    int w = tid >> 5, l = tid & 31;
    int g = l >> 2, t = l & 3;

    if (IN_BN && tid < D) {
        float mu  = statsIn[tid] * inv_n;
        float var = statsIn[D + tid] * inv_n - mu * mu;
        float rs  = rsqrtf(var + BN_EPS);
        float a   = rs * gg[tid];
        ssa[tid] = a; ssb[tid] = be[tid] - mu * a;
    }
    if (STATS && tid < 2 * D) sbuf[tid] = 0.f;
    if (GATHER && tid <= RPB) {
        int node = base + tid;
        rp[tid] = (node <= rows) ? __ldg(&g_rowptr[node]) : 0;
    }

    // C fragments: 8 n-tiles x 4 regs, init with bias.
    float c[8][4];
    #pragma unroll
    for (int nt = 0; nt < 8; nt++) {
        float2 b2 = *(const float2*)(bias + nt * 8 + 2 * t);
        c[nt][0] = b2.x; c[nt][1] = b2.y; c[nt][2] = b2.x; c[nt][3] = b2.y;
    }

    int r0g = base + w * 16 + g, r1g = r0g + 8;   // this thread's global rows
    bool v0 = (r0g < rows), v1 = (r1g < rows);

    for (int ps = 0; ps < NPASS; ps++) {
        __syncthreads();
        // ---- stage W into fragment-order hi/lo arrays ----
        {
            const float* Wp = W + (size_t)ps * wStride;
            for (int i = tid; i < 2048; i += 256) {
                int ent = i >> 5, ll = i & 31;
                int ks = ent >> 3, nt = ent & 7;
                int k0 = ks * 8 + (ll & 3), n = nt * 8 + (ll >> 2);
                float w0 = __ldg(&Wp[k0 * D + n]);
                float w1 = __ldg(&Wp[(k0 + 4) * D + n]);
                uint32_t h0 = cvt_tf32(w0), h1 = cvt_tf32(w1);
                uint32_t l0 = cvt_tf32(w0 - __uint_as_float(h0));
                uint32_t l1 = cvt_tf32(w1 - __uint_as_float(h1));
                WBh[i] = (ull)h0 | ((ull)h1 << 32);
                WBl[i] = (ull)l0 | ((ull)l1 << 32);
            }
        }
        // ---- stage Hs (gather path only) ----
        if (GATHER) {
            int cc = (tid & 15) << 2;
            #pragma unroll
            for (int b = 0; b < 8; b++) {
                int n = b * 16 + (tid >> 4);
                int node = base + n;
                if (node < rows) {
                    int beg = rp[n], end = rp[n + 1];
                    float4 acc = *(const float4*)(X + (size_t)node * D + cc);
                    int e = beg;
                    int i0, i1, i2, i3;
                    bool have = (e + 3 < end);
                    if (have) {
                        i0 = __ldg(&g_csr[e]);     i1 = __ldg(&g_csr[e + 1]);
                        i2 = __ldg(&g_csr[e + 2]); i3 = __ldg(&g_csr[e + 3]);
                    }
                    while (have) {
                        int en = e + 4;
                        bool hn = (en + 3 < end);
                        int j0, j1, j2, j3;
                        if (hn) {
                            j0 = __ldg(&g_csr[en]);     j1 = __ldg(&g_csr[en + 1]);
                            j2 = __ldg(&g_csr[en + 2]); j3 = __ldg(&g_csr[en + 3]);
                        }
                        float4 v0f = *(const float4*)(X + (size_t)i0 * D + cc);
                        float4 v1f = *(const float4*)(X + (size_t)i1 * D + cc);
                        float4 v2f = *(const float4*)(X + (size_t)i2 * D + cc);
                        float4 v3f = *(const float4*)(X + (size_t)i3 * D + cc);
                        acc.x += (v0f.x + v1f.x) + (v2f.x + v3f.x);
                        acc.y += (v0f.y + v1f.y) + (v2f.y + v3f.y);
                        acc.z += (v0f.z + v1f.z) + (v2f.z + v3f.z);
                        acc.w += (v0f.w + v1f.w) + (v2f.w + v3f.w);
                        e = en; have = hn;
                        i0 = j0; i1 = j1; i2 = j2; i3 = j3;
                    }
                    for (; e < end; e++) {
                        int s0 = __ldg(&g_csr[e]);
                        float4 v0f = *(const float4*)(X + (size_t)s0 * D + cc);
                        acc.x += v0f.x; acc.y += v0f.y; acc.z += v0f.z; acc.w += v0f.w;
                    }
                    *(float4*)(Hs + n * HS + cc) = acc;
                }
            }
        }
        __syncthreads();

        // ---- MMA mainloop ----
        const float* ar0 = GATHER ? (Hs + (w * 16 + g) * HS) : nullptr;
        const float* ar1 = GATHER ? (ar0 + 8 * HS) : nullptr;
        const float* Xr0 = GATHER ? nullptr : (X + (size_t)ps * xStride + (size_t)r0g * D);
        const float* Xr1 = GATHER ? nullptr : (X + (size_t)ps * xStride + (size_t)r1g * D);
        #pragma unroll
        for (int ks = 0; ks < 8; ks++) {
            int kc = ks * 8 + t;
            float x00, x01, x10, x11;
            if (GATHER) {
                x00 = ar0[kc]; x01 = ar0[kc + 4];
                x10 = ar1[kc]; x11 = ar1[kc + 4];
            } else {
                x00 = v0 ? __ldg(Xr0 + kc)     : 0.f;
                x01 = v0 ? __ldg(Xr0 + kc + 4) : 0.f;
                x10 = v1 ? __ldg(Xr1 + kc)     : 0.f;
                x11 = v1 ? __ldg(Xr1 + kc + 4) : 0.f;
                if (IN_BN) {
                    x00 = fmaxf(x00 * ssa[kc]     + ssb[kc],     0.f);
                    x01 = fmaxf(x01 * ssa[kc + 4] + ssb[kc + 4], 0.f);
                    x10 = fmaxf(x10 * ssa[kc]     + ssb[kc],     0.f);
                    x11 = fmaxf(x11 * ssa[kc + 4] + ssb[kc + 4], 0.f);
                }
            }
            uint32_t ah0 = cvt_tf32(x00), ah1 = cvt_tf32(x10);
            uint32_t ah2 = cvt_tf32(x01), ah3 = cvt_tf32(x11);
            uint32_t al0 = cvt_tf32(x00 - __uint_as_float(ah0));
            uint32_t al1 = cvt_tf32(x10 - __uint_as_float(ah1));
            uint32_t al2 = cvt_tf32(x01 - __uint_as_float(ah2));
            uint32_t al3 = cvt_tf32(x11 - __uint_as_float(ah3));
            #pragma unroll
            for (int nt = 0; nt < 8; nt++) {
                ull bh = WBh[(ks * 8 + nt) * 32 + l];
                ull bl = WBl[(ks * 8 + nt) * 32 + l];
                uint32_t bh0 = (uint32_t)bh, bh1 = (uint32_t)(bh >> 32);
                uint32_t bl0 = (uint32_t)bl, bl1 = (uint32_t)(bl >> 32);
                mma_tf32(c[nt], ah0, ah1, ah2, ah3, bh0, bh1);
                mma_tf32(c[nt], al0, al1, al2, al3, bh0, bh1);
                mma_tf32(c[nt], ah0, ah1, ah2, ah3, bl0, bl1);
            }
        }
    }

    // ---- store ----
    #pragma unroll
    for (int nt = 0; nt < 8; nt++) {
        int col = nt * 8 + 2 * t;
        if (v0) {
            float2 o = make_float2(c[nt][0], c[nt][1]);
            if (OUT_RELU) { o.x = fmaxf(o.x, 0.f); o.y = fmaxf(o.y, 0.f); }
            *(float2*)(O + (size_t)r0g * D + col) = o;
        }
        if (v1) {
            float2 o = make_float2(c[nt][2], c[nt][3]);
            if (OUT_RELU) { o.x = fmaxf(o.x, 0.f); o.y = fmaxf(o.y, 0.f); }
            *(float2*)(O + (size_t)r1g * D + col) = o;
        }
    }

    if (STATS) {
        #pragma unroll
        for (int nt = 0; nt < 8; nt++) {
            float e0 = v0 ? c[nt][0] : 0.f, e1 = v0 ? c[nt][1] : 0.f;
            float e2 = v1 ? c[nt][2] : 0.f, e3 = v1 ? c[nt][3] : 0.f;
            float s0 = e0 + e2, s1 = e1 + e3;
            float q0 = e0 * e0 + e2 * e2, q1 = e1 * e1 + e3 * e3;
            #pragma unroll
            for (int off = 4; off < 32; off <<= 1) {
                s0 += __shfl_xor_sync(0xffffffff, s0, off);
                s1 += __shfl_xor_sync(0xffffffff, s1, off);
                q0 += __shfl_xor_sync(0xffffffff, q0, off);
                q1 += __shfl_xor_sync(0xffffffff, q1, off);
            }
            if (l < 4) {
                int col = nt * 8 + 2 * t;
                atomicAdd(&sbuf[col],         s0);
                atomicAdd(&sbuf[col + 1],     s1);
                atomicAdd(&sbuf[D + col],     q0);
                atomicAdd(&sbuf[D + col + 1], q1);
            }
        }
        __syncthreads();
        if (tid < 2 * D) atomicAdd(&statsOut[tid], sbuf[tid]);
    }
}

// segmented pool
__global__ void k_pool_seg(const float* __restrict__ XJ) {
    int t = blockIdx.x * 256 + threadIdx.x;
    int m = t >> 4;
    if (m >= NM) return;
    int c = (t & 15) << 2;
    int beg = g_molptr[m], end = g_molptr[m + 1];
    float4 acc = make_float4(0.f, 0.f, 0.f, 0.f);
    for (int n = beg; n < end; n++) {
        float4 v = *(const float4*)(XJ + (size_t)n * D + c);
        acc.x += v.x; acc.y += v.y; acc.z += v.z; acc.w += v.w;
    }
    *(float4*)(g_G + (size_t)m * D + c) = acc;
}

// out = relu(TG*bn) @ (W2 @ oW) + (b2 @ oW + ob)
__global__ __launch_bounds__(256) void k_final(
    const float* __restrict__ W2, const float* __restrict__ oW,
    const float* __restrict__ b2, const float* __restrict__ ob,
    const float* __restrict__ gg, const float* __restrict__ be,
    float* __restrict__ out, int rows)
{
    __shared__ float Ws[D * NO];
    __shared__ float bcs[NO], sa[D], sb[D];
    int tid = threadIdx.x;
    const float* statsIn = g_stats + 3 * 2 * D;
    for (int i = tid; i < D * NO; i += 256) {
        int k = i / NO, o = i % NO;
        float sum = 0.f;
        for (int j = 0; j < D; j++) sum += W2[k * D + j] * oW[j * NO + o];
        Ws[i] = sum;
    }
    if (tid < NO) {
        float sum = ob[tid];
        for (int j = 0; j < D; j++) sum += b2[j] * oW[j * NO + tid];
        bcs[tid] = sum;
    }
    if (tid < D) {
        float mu  = statsIn[tid] * (1.0f / NM);
        float var = statsIn[D + tid] * (1.0f / NM) - mu * mu;
        float rs  = rsqrtf(var + BN_EPS);
        float a   = rs * gg[tid];
        sa[tid] = a; sb[tid] = be[tid] - mu * a;
    }
    __syncthreads();
    int row = blockIdx.x * 256 + tid;
    if (row >= rows) return;
    float acc[NO];
    #pragma unroll
    for (int o = 0; o < NO; o++) acc[o] = bcs[o];
    const float* tr = g_TG + (size_t)row * D;
    for (int k = 0; k < D; k++) {
        float h = fmaxf(tr[k] * sa[k] + sb[k], 0.f);
        #pragma unroll
        for (int o = 0; o < NO; o++) acc[o] += h * Ws[k * NO + o];
    }
    float* orow = out + (size_t)row * NO;
    #pragma unroll
    for (int o = 0; o < NO; o++) orow[o] = acc[o];
}

// ---------------- host ----------------
extern "C" void kernel_launch(void* const* d_in, const int* in_sizes, int n_in,
                              void* d_out, int out_size)
{
    const int*   atom_ids = (const int*)  d_in[0];
    const int*   edge     = (const int*)  d_in[1];
    const int*   mol_ids  = (const int*)  d_in[2];
    const float* emb_W    = (const float*)d_in[3];
    const float* gin_W1   = (const float*)d_in[4];
    const float* gin_b1   = (const float*)d_in[5];
    const float* gin_g1   = (const float*)d_in[6];
    const float* gin_be1  = (const float*)d_in[7];
    const float* gin_W2   = (const float*)d_in[8];
    const float* gin_b2   = (const float*)d_in[9];
    const float* jk_W     = (const float*)d_in[10];
    const float* jk_b     = (const float*)d_in[11];
    const float* ffn_W1   = (const float*)d_in[12];
    const float* ffn_b1   = (const float*)d_in[13];
    const float* ffn_g    = (const float*)d_in[14];
    const float* ffn_be   = (const float*)d_in[15];
    const float* ffn_W2   = (const float*)d_in[16];
    const float* ffn_b2   = (const float*)d_in[17];
    const float* out_W    = (const float*)d_in[18];
    const float* out_b    = (const float*)d_in[19];
    float* out = (float*)d_out;

    const int* src = edge;
    const int* dst = edge + NE;

    float *X0, *T, *XS, *G, *TG, *stats;
    cudaGetSymbolAddress((void**)&X0,    g_X0);
    cudaGetSymbolAddress((void**)&T,     g_T);
    cudaGetSymbolAddress((void**)&XS,    g_XS);
    cudaGetSymbolAddress((void**)&G,     g_G);
    cudaGetSymbolAddress((void**)&TG,    g_TG);
    cudaGetSymbolAddress((void**)&stats, g_stats);

    cudaFuncSetAttribute(k_gemm<1,0,0,1,1>, cudaFuncAttributeMaxDynamicSharedMemorySize, SMEM_GA);
    cudaFuncSetAttribute(k_gemm<0,1,1,0,1>, cudaFuncAttributeMaxDynamicSharedMemorySize, SMEM_WB);
    cudaFuncSetAttribute(k_gemm<0,0,0,0,NL>, cudaFuncAttributeMaxDynamicSharedMemorySize, SMEM_WB);
    cudaFuncSetAttribute(k_gemm<0,0,0,1,1>, cudaFuncAttributeMaxDynamicSharedMemorySize, SMEM_WB);

    k_init<<<(NN + 255)/256, 256>>>();
    k_embed<<<(NN*16 + 255)/256, 256>>>(atom_ids, emb_W);
    {
        void* args[] = { (void*)&src, (void*)&dst };
        cudaLaunchCooperativeKernel((void*)k_csr_coop, dim3(COOP_BLOCKS), dim3(256),
                                    args, 0, (cudaStream_t)0);
    }

    const int GRID = (NN + RPB - 1) / RPB;
    for (int l = 0; l < NL; l++) {
        const float* xin = (l == 0) ? X0 : XS + (size_t)(l-1) * NN * D;
        float* slot = stats + (size_t)l * 2 * D;
        // gemm1: gather + GEMM + stats -> T
        k_gemm<1,0,0,1,1><<<GRID, 256, SMEM_GA>>>(
            xin, gin_W1 + (size_t)l*D*D, gin_b1 + l*D, T, NN,
            nullptr, slot, nullptr, nullptr, 0.f, 0, 0);
        // gemm2: direct-A BN+relu GEMM + relu -> XS[l]
        k_gemm<0,1,1,0,1><<<GRID, 256, SMEM_WB>>>(
            T, gin_W2 + (size_t)l*D*D, gin_b2 + l*D, XS + (size_t)l*NN*D, NN,
            slot, nullptr, gin_g1 + l*D, gin_be1 + l*D, 1.0f / NN, 0, 0);
    }

    k_molptr<<<(NN + 255)/256, 256>>>(mol_ids);
    // JK: 3-pass accumulate -> X0
    k_gemm<0,0,0,0,NL><<<GRID, 256, SMEM_WB>>>(
        XS, jk_W, jk_b, X0, NN,
        nullptr, nullptr, nullptr, nullptr, 0.f, (size_t)NN * D, (size_t)D * D);

    k_pool_seg<<<(NM*16 + 255)/256, 256>>>(X0);

    float* slot3 = stats + 3 * 2 * D;
    k_gemm<0,0,0,1,1><<<(NM + RPB - 1)/RPB, 256, SMEM_WB>>>(
        G, ffn_W1, ffn_b1, TG, NM,
        nullptr, slot3, nullptr, nullptr, 0.f, 0, 0);

    k_final<<<(NM + 255)/256, 256>>>(ffn_W2, out_W, ffn_b2, out_b,
                                     ffn_g, ffn_be, out, NM);
}

// round 15
// speedup vs baseline: 1.4948x; 1.0352x over previous
#include <cuda_runtime.h>
#include <cooperative_groups.h>
namespace cg = cooperative_groups;

#define NN 100000
#define NE 1200000
#define D 64
#define NL 3
#define NM 5000
#define NO 24
#define BN_EPS 1e-5f
#define NB_SCAN ((NN + 1023) / 1024)
#define HS 68
#define COOP_BLOCKS 592
#define SMEM_WB (2 * 2048 * 8)                   // 32768 B (W fragments hi+lo)
#define RPB_GA 96
#define NT_GA  384
#define SMEM_GA (RPB_GA * HS * 4 + SMEM_WB)      // 58880 B (gather path)
#define RPB_NG 128
#define NT_NG  256

typedef unsigned long long ull;

// ---------------- scratch ----------------
__device__ __align__(128) float g_X0 [NN * D];
__device__ __align__(128) float g_T  [NN * D];
__device__ __align__(128) float g_XS [NL * NN * D];
__device__ __align__(128) float g_G  [NM * D];
__device__ __align__(128) float g_TG [NM * D];
__device__ __align__(128) float g_stats[4 * 2 * D];
__device__ __align__(128) int g_deg   [NN];
__device__ __align__(128) int g_cur   [NN];
__device__ __align__(128) int g_rowptr[NN + 1];
__device__ __align__(128) int g_csr   [NE];
__device__ __align__(128) int g_bsum  [NB_SCAN];
__device__ __align__(128) int g_boff  [NB_SCAN];
__device__ __align__(128) int g_molptr[NM + 1];

// ---------------- helpers ----------------
__device__ __forceinline__ uint32_t cvt_tf32(float x) {
    uint32_t r; asm("cvt.rna.tf32.f32 %0, %1;" : "=r"(r) : "f"(x)); return r;
}
__device__ __forceinline__ void mma_tf32(float* c, uint32_t a0, uint32_t a1,
                                         uint32_t a2, uint32_t a3,
                                         uint32_t b0, uint32_t b1) {
    asm volatile(
        "mma.sync.aligned.m16n8k8.row.col.f32.tf32.tf32.f32 "
        "{%0,%1,%2,%3},{%4,%5,%6,%7},{%8,%9},{%0,%1,%2,%3};"
        : "+f"(c[0]), "+f"(c[1]), "+f"(c[2]), "+f"(c[3])
        : "r"(a0), "r"(a1), "r"(a2), "r"(a3), "r"(b0), "r"(b1));
}

// ---------------- init ----------------
__global__ void k_init() {
    int t = blockIdx.x * blockDim.x + threadIdx.x;
    if (t < NN) { g_deg[t] = 0; g_cur[t] = 0; }
    if (t < 4 * 2 * D) g_stats[t] = 0.f;
}

__global__ void k_embed(const int* __restrict__ atom_ids, const float* __restrict__ embW) {
    int t = blockIdx.x * blockDim.x + threadIdx.x;
    if (t >= NN * 16) return;
    int n = t >> 4, c = (t & 15) << 2;
    int a = __ldg(atom_ids + n);
    *(float4*)(g_X0 + (size_t)n * D + c) = *(const float4*)(embW + (size_t)a * D + c);
}

// ---------------- cooperative CSR build -----------------
__global__ void k_csr_coop(const int* __restrict__ src, const int* __restrict__ dst) {
    cg::grid_group grid = cg::this_grid();
    int tid = threadIdx.x, bid = blockIdx.x;
    int gt = bid * 256 + tid, gs = gridDim.x * 256;

    for (int e = gt; e < NE; e += gs) atomicAdd(&g_deg[__ldg(dst + e)], 1);
    grid.sync();

    __shared__ int sh[256];
    if (bid < NB_SCAN) {
        int base = bid * 1024;
        int loc[4]; int s = 0;
        #pragma unroll
        for (int j = 0; j < 4; j++) {
            int i = base + tid * 4 + j;
            int v = (i < NN) ? g_deg[i] : 0;
            s += v; loc[j] = s;
        }
        int excl_in = s;
        sh[tid] = excl_in; __syncthreads();
        for (int off = 1; off < 256; off <<= 1) {
            int t2 = (tid >= off) ? sh[tid - off] : 0;
            __syncthreads();
            sh[tid] += t2;
            __syncthreads();
        }
        int pre = sh[tid] - excl_in;
        #pragma unroll
        for (int j = 0; j < 4; j++) {
            int i = base + tid * 4 + j;
            if (i < NN) g_rowptr[i + 1] = pre + loc[j];
        }
        if (tid == 255) g_bsum[bid] = sh[255];
    }
    grid.sync();

    if (bid == 0 && tid < 32) {
        int carry = 0;
        for (int b = 0; b < NB_SCAN; b += 32) {
            int idx = b + tid;
            int v = (idx < NB_SCAN) ? g_bsum[idx] : 0;
            int x = v;
            #pragma unroll
            for (int off = 1; off < 32; off <<= 1) {
                int y = __shfl_up_sync(0xffffffff, x, off);
                if (tid >= off) x += y;
            }
            if (idx < NB_SCAN) g_boff[idx] = carry + x - v;
            carry += __shfl_sync(0xffffffff, x, 31);
        }
    }
    grid.sync();

    if (gt == 0) g_rowptr[0] = 0;
    for (int i = gt; i < NN; i += gs) g_rowptr[i + 1] += g_boff[i >> 10];
    grid.sync();

    for (int e = gt; e < NE; e += gs) {
        int d = __ldg(dst + e);
        int pos = g_rowptr[d] + atomicAdd(&g_cur[d], 1);
        g_csr[pos] = __ldg(src + e);
    }
}

__global__ void k_molptr(const int* __restrict__ mol) {
    int t = blockIdx.x * blockDim.x + threadIdx.x;
    if (t >= NN) return;
    int m1 = __ldg(mol + t);
    int m0 = (t == 0) ? -1 : __ldg(mol + t - 1);
    for (int m = m0 + 1; m <= m1; m++) g_molptr[m] = t;
    if (t == NN - 1)
        for (int m = m1 + 1; m <= NM; m++) g_molptr[m] = NN;
}

// ============================================================================
// Unified GEMM kernel (mma.sync tf32, 3xTF32), parametrized block geometry.
// NT threads, RPBt rows/block; WPT = warps per 16-row m-tile (1 or 2).
// ============================================================================
template<int NT, int RPBt, int GATHER, int IN_BN, int OUT_RELU, int STATS, int NPASS>
__global__ __launch_bounds__(NT) void k_gemm(
    const float* __restrict__ X, const float* __restrict__ W,
    const float* __restrict__ bias, float* __restrict__ O, int rows,
    const float* __restrict__ statsIn, float* __restrict__ statsOut,
    const float* __restrict__ gg, const float* __restrict__ be, float inv_n,
    size_t xStride, size_t wStride)
{
    constexpr int NWARP = NT / 32;
    constexpr int NMT   = RPBt / 16;        // m-tiles per block
    constexpr int WPT   = NWARP / NMT;      // warps per m-tile
    constexpr int NTN   = 8 / WPT;          // n-tiles per warp

    extern __shared__ __align__(16) float dsm[];
    float* Hs  = dsm;
    ull*   WBh = (ull*)(GATHER ? (dsm + RPBt * HS) : dsm);
    ull*   WBl = WBh + 2048;
    __shared__ float ssa[D], ssb[D];
    __shared__ float sbuf[2 * D];
    __shared__ int   rp[RPB_NG + 1];
    int tid = threadIdx.x;
    int base = blockIdx.x * RPBt;
    int w = tid >> 5, l = tid & 31;
    int g = l >> 2, t = l & 3;
    int mt = w / WPT, nt0 = (w % WPT) * NTN;

    if (IN_BN && tid < D) {
        float mu  = statsIn[tid] * inv_n;
        float var = statsIn[D + tid] * inv_n - mu * mu;
        float rs  = rsqrtf(var + BN_EPS);
        float a   = rs * gg[tid];
        ssa[tid] = a; ssb[tid] = be[tid] - mu * a;
    }
    if (STATS && tid < 2 * D) sbuf[tid] = 0.f;
    if (GATHER && tid <= RPBt) {
        int node = base + tid;
        rp[tid] = (node <= rows) ? __ldg(&g_rowptr[node]) : 0;
    }

    float c[NTN][4];
    #pragma unroll
    for (int q = 0; q < NTN; q++) {
        float2 b2 = *(const float2*)(bias + (nt0 + q) * 8 + 2 * t);
        c[q][0] = b2.x; c[q][1] = b2.y; c[q][2] = b2.x; c[q][3] = b2.y;
    }

    int r0g = base + mt * 16 + g, r1g = r0g + 8;
    bool v0 = (r0g < rows), v1 = (r1g < rows);

    for (int ps = 0; ps < NPASS; ps++) {
        __syncthreads();
        // ---- stage W fragments ----
        {
            const float* Wp = W + (size_t)ps * wStride;
            for (int i = tid; i < 2048; i += NT) {
                int ent = i >> 5, ll = i & 31;
                int ks = ent >> 3, nt = ent & 7;
                int k0 = ks * 8 + (ll & 3), n = nt * 8 + (ll >> 2);
                float w0 = __ldg(&Wp[k0 * D + n]);
                float w1 = __ldg(&Wp[(k0 + 4) * D + n]);
                uint32_t h0 = cvt_tf32(w0), h1 = cvt_tf32(w1);
                uint32_t l0 = cvt_tf32(w0 - __uint_as_float(h0));
                uint32_t l1 = cvt_tf32(w1 - __uint_as_float(h1));
                WBh[i] = (ull)h0 | ((ull)h1 << 32);
                WBl[i] = (ull)l0 | ((ull)l1 << 32);
            }
        }
        // ---- stage Hs (gather) ----
        if (GATHER) {
            constexpr int NPB = NT / 16;            // nodes per batch
            constexpr int NB  = RPBt * 16 / NT;     // batches
            int cc = (tid & 15) << 2;
            #pragma unroll
            for (int b = 0; b < NB; b++) {
                int n = b * NPB + (tid >> 4);
                int node = base + n;
                if (node < rows) {
                    int beg = rp[n], end = rp[n + 1];
                    float4 acc = *(const float4*)(X + (size_t)node * D + cc);
                    int e = beg;
                    int i0, i1, i2, i3;
                    bool have = (e + 3 < end);
                    if (have) {
                        i0 = __ldg(&g_csr[e]);     i1 = __ldg(&g_csr[e + 1]);
                        i2 = __ldg(&g_csr[e + 2]); i3 = __ldg(&g_csr[e + 3]);
                    }
                    while (have) {
                        int en = e + 4;
                        bool hn = (en + 3 < end);
                        int j0, j1, j2, j3;
                        if (hn) {
                            j0 = __ldg(&g_csr[en]);     j1 = __ldg(&g_csr[en + 1]);
                            j2 = __ldg(&g_csr[en + 2]); j3 = __ldg(&g_csr[en + 3]);
                        }
                        float4 v0f = *(const float4*)(X + (size_t)i0 * D + cc);
                        float4 v1f = *(const float4*)(X + (size_t)i1 * D + cc);
                        float4 v2f = *(const float4*)(X + (size_t)i2 * D + cc);
                        float4 v3f = *(const float4*)(X + (size_t)i3 * D + cc);
                        acc.x += (v0f.x + v1f.x) + (v2f.x + v3f.x);
                        acc.y += (v0f.y + v1f.y) + (v2f.y + v3f.y);
                        acc.z += (v0f.z + v1f.z) + (v2f.z + v3f.z);
                        acc.w += (v0f.w + v1f.w) + (v2f.w + v3f.w);
                        e = en; have = hn;
                        i0 = j0; i1 = j1; i2 = j2; i3 = j3;
                    }
                    for (; e < end; e++) {
                        int s0 = __ldg(&g_csr[e]);
                        float4 v0f = *(const float4*)(X + (size_t)s0 * D + cc);
                        acc.x += v0f.x; acc.y += v0f.y; acc.z += v0f.z; acc.w += v0f.w;
                    }
                    *(float4*)(Hs + n * HS + cc) = acc;
                }
            }
        }
        __syncthreads();

        // ---- MMA mainloop ----
        const float* ar0 = GATHER ? (Hs + (mt * 16 + g) * HS) : nullptr;
        const float* ar1 = GATHER ? (ar0 + 8 * HS) : nullptr;
        const float* Xr0 = GATHER ? nullptr : (X + (size_t)ps * xStride + (size_t)r0g * D);
        const float* Xr1 = GATHER ? nullptr : (X + (size_t)ps * xStride + (size_t)r1g * D);
        #pragma unroll
        for (int ks = 0; ks < 8; ks++) {
            int kc = ks * 8 + t;
            float x00, x01, x10, x11;
            if (GATHER) {
                x00 = ar0[kc]; x01 = ar0[kc + 4];
                x10 = ar1[kc]; x11 = ar1[kc + 4];
            } else {
                x00 = v0 ? __ldg(Xr0 + kc)     : 0.f;
                x01 = v0 ? __ldg(Xr0 + kc + 4) : 0.f;
                x10 = v1 ? __ldg(Xr1 + kc)     : 0.f;
                x11 = v1 ? __ldg(Xr1 + kc + 4) : 0.f;
                if (IN_BN) {
                    x00 = fmaxf(x00 * ssa[kc]     + ssb[kc],     0.f);
                    x01 = fmaxf(x01 * ssa[kc + 4] + ssb[kc + 4], 0.f);
                    x10 = fmaxf(x10 * ssa[kc]     + ssb[kc],     0.f);
                    x11 = fmaxf(x11 * ssa[kc + 4] + ssb[kc + 4], 0.f);
                }
            }
            uint32_t ah0 = cvt_tf32(x00), ah1 = cvt_tf32(x10);
            uint32_t ah2 = cvt_tf32(x01), ah3 = cvt_tf32(x11);
            uint32_t al0 = cvt_tf32(x00 - __uint_as_float(ah0));
            uint32_t al1 = cvt_tf32(x10 - __uint_as_float(ah1));
            uint32_t al2 = cvt_tf32(x01 - __uint_as_float(ah2));
            uint32_t al3 = cvt_tf32(x11 - __uint_as_float(ah3));
            #pragma unroll
            for (int q = 0; q < NTN; q++) {
                int nt = nt0 + q;
                ull bh = WBh[(ks * 8 + nt) * 32 + l];
                ull bl = WBl[(ks * 8 + nt) * 32 + l];
                uint32_t bh0 = (uint32_t)bh, bh1 = (uint32_t)(bh >> 32);
                uint32_t bl0 = (uint32_t)bl, bl1 = (uint32_t)(bl >> 32);
                mma_tf32(c[q], ah0, ah1, ah2, ah3, bh0, bh1);
                mma_tf32(c[q], al0, al1, al2, al3, bh0, bh1);
                mma_tf32(c[q], ah0, ah1, ah2, ah3, bl0, bl1);
            }
        }
    }

    // ---- store ----
    #pragma unroll
    for (int q = 0; q < NTN; q++) {
        int col = (nt0 + q) * 8 + 2 * t;
        if (v0) {
            float2 o = make_float2(c[q][0], c[q][1]);
            if (OUT_RELU) { o.x = fmaxf(o.x, 0.f); o.y = fmaxf(o.y, 0.f); }
            *(float2*)(O + (size_t)r0g * D + col) = o;
        }
        if (v1) {
            float2 o = make_float2(c[q][2], c[q][3]);
            if (OUT_RELU) { o.x = fmaxf(o.x, 0.f); o.y = fmaxf(o.y, 0.f); }
            *(float2*)(O + (size_t)r1g * D + col) = o;
        }
    }

    if (STATS) {
        #pragma unroll
        for (int q = 0; q < NTN; q++) {
            float e0 = v0 ? c[q][0] : 0.f, e1 = v0 ? c[q][1] : 0.f;
            float e2 = v1 ? c[q][2] : 0.f, e3 = v1 ? c[q][3] : 0.f;
            float s0 = e0 + e2, s1 = e1 + e3;
            float q0 = e0 * e0 + e2 * e2, q1 = e1 * e1 + e3 * e3;
            #pragma unroll
            for (int off = 4; off < 32; off <<= 1) {
                s0 += __shfl_xor_sync(0xffffffff, s0, off);
                s1 += __shfl_xor_sync(0xffffffff, s1, off);
                q0 += __shfl_xor_sync(0xffffffff, q0, off);
                q1 += __shfl_xor_sync(0xffffffff, q1, off);
            }
            if (l < 4) {
                int col = (nt0 + q) * 8 + 2 * t;
                atomicAdd(&sbuf[col],         s0);
                atomicAdd(&sbuf[col + 1],     s1);
                atomicAdd(&sbuf[D + col],     q0);
                atomicAdd(&sbuf[D + col + 1], q1);
            }
        }
        __syncthreads();
        if (tid < 2 * D) atomicAdd(&statsOut[tid], sbuf[tid]);
    }
}

// segmented pool
__global__ void k_pool_seg(const float* __restrict__ XJ) {
    int t = blockIdx.x * 256 + threadIdx.x;
    int m = t >> 4;
    if (m >= NM) return;
    int c = (t & 15) << 2;
    int beg = g_molptr[m], end = g_molptr[m + 1];
    float4 acc = make_float4(0.f, 0.f, 0.f, 0.f);
    for (int n = beg; n < end; n++) {
        float4 v = *(const float4*)(XJ + (size_t)n * D + c);
        acc.x += v.x; acc.y += v.y; acc.z += v.z; acc.w += v.w;
    }
    *(float4*)(g_G + (size_t)m * D + c) = acc;
}

// out = relu(TG*bn) @ (W2 @ oW) + (b2 @ oW + ob)
__global__ __launch_bounds__(256) void k_final(
    const float* __restrict__ W2, const float* __restrict__ oW,
    const float* __restrict__ b2, const float* __restrict__ ob,
    const float* __restrict__ gg, const float* __restrict__ be,
    float* __restrict__ out, int rows)
{
    __shared__ float Ws[D * NO];
    __shared__ float bcs[NO], sa[D], sb[D];
    int tid = threadIdx.x;
    const float* statsIn = g_stats + 3 * 2 * D;
    for (int i = tid; i < D * NO; i += 256) {
        int k = i / NO, o = i % NO;
        float sum = 0.f;
        for (int j = 0; j < D; j++) sum += W2[k * D + j] * oW[j * NO + o];
        Ws[i] = sum;
    }
    if (tid < NO) {
        float sum = ob[tid];
        for (int j = 0; j < D; j++) sum += b2[j] * oW[j * NO + tid];
        bcs[tid] = sum;
    }
    if (tid < D) {
        float mu  = statsIn[tid] * (1.0f / NM);
        float var = statsIn[D + tid] * (1.0f / NM) - mu * mu;
        float rs  = rsqrtf(var + BN_EPS);
        float a   = rs * gg[tid];
        sa[tid] = a; sb[tid] = be[tid] - mu * a;
    }
    __syncthreads();
    int row = blockIdx.x * 256 + tid;
    if (row >= rows) return;
    float acc[NO];
    #pragma unroll
    for (int o = 0; o < NO; o++) acc[o] = bcs[o];
    const float* tr = g_TG + (size_t)row * D;
    for (int k = 0; k < D; k++) {
        float h = fmaxf(tr[k] * sa[k] + sb[k], 0.f);
        #pragma unroll
        for (int o = 0; o < NO; o++) acc[o] += h * Ws[k * NO + o];
    }
    float* orow = out + (size_t)row * NO;
    #pragma unroll
    for (int o = 0; o < NO; o++) orow[o] = acc[o];
}

// ---------------- host ----------------
extern "C" void kernel_launch(void* const* d_in, const int* in_sizes, int n_in,
                              void* d_out, int out_size)
{
    const int*   atom_ids = (const int*)  d_in[0];
    const int*   edge     = (const int*)  d_in[1];
    const int*   mol_ids  = (const int*)  d_in[2];
    const float* emb_W    = (const float*)d_in[3];
    const float* gin_W1   = (const float*)d_in[4];
    const float* gin_b1   = (const float*)d_in[5];
    const float* gin_g1   = (const float*)d_in[6];
    const float* gin_be1  = (const float*)d_in[7];
    const float* gin_W2   = (const float*)d_in[8];
    const float* gin_b2   = (const float*)d_in[9];
    const float* jk_W     = (const float*)d_in[10];
    const float* jk_b     = (const float*)d_in[11];
    const float* ffn_W1   = (const float*)d_in[12];
    const float* ffn_b1   = (const float*)d_in[13];
    const float* ffn_g    = (const float*)d_in[14];
    const float* ffn_be   = (const float*)d_in[15];
    const float* ffn_W2   = (const float*)d_in[16];
    const float* ffn_b2   = (const float*)d_in[17];
    const float* out_W    = (const float*)d_in[18];
    const float* out_b    = (const float*)d_in[19];
    float* out = (float*)d_out;

    const int* src = edge;
    const int* dst = edge + NE;

    float *X0, *T, *XS, *G, *TG, *stats;
    cudaGetSymbolAddress((void**)&X0,    g_X0);
    cudaGetSymbolAddress((void**)&T,     g_T);
    cudaGetSymbolAddress((void**)&XS,    g_XS);
    cudaGetSymbolAddress((void**)&G,     g_G);
    cudaGetSymbolAddress((void**)&TG,    g_TG);
    cudaGetSymbolAddress((void**)&stats, g_stats);

    cudaFuncSetAttribute(k_gemm<NT_GA,RPB_GA,1,0,0,1,1>,
                         cudaFuncAttributeMaxDynamicSharedMemorySize, SMEM_GA);
    cudaFuncSetAttribute(k_gemm<NT_NG,RPB_NG,0,1,1,0,1>,
                         cudaFuncAttributeMaxDynamicSharedMemorySize, SMEM_WB);
    cudaFuncSetAttribute(k_gemm<NT_NG,RPB_NG,0,0,0,0,NL>,
                         cudaFuncAttributeMaxDynamicSharedMemorySize, SMEM_WB);
    cudaFuncSetAttribute(k_gemm<NT_NG,RPB_NG,0,0,0,1,1>,
                         cudaFuncAttributeMaxDynamicSharedMemorySize, SMEM_WB);

    k_init<<<(NN + 255)/256, 256>>>();
    k_embed<<<(NN*16 + 255)/256, 256>>>(atom_ids, emb_W);
    {
        void* args[] = { (void*)&src, (void*)&dst };
        cudaLaunchCooperativeKernel((void*)k_csr_coop, dim3(COOP_BLOCKS), dim3(256),
                                    args, 0, (cudaStream_t)0);
    }

    const int GRID_GA = (NN + RPB_GA - 1) / RPB_GA;
    const int GRID_NG = (NN + RPB_NG - 1) / RPB_NG;
    for (int l = 0; l < NL; l++) {
        const float* xin = (l == 0) ? X0 : XS + (size_t)(l-1) * NN * D;
        float* slot = stats + (size_t)l * 2 * D;
        // gemm1: gather + GEMM + stats -> T   (384 threads, 96 rows)
        k_gemm<NT_GA,RPB_GA,1,0,0,1,1><<<GRID_GA, NT_GA, SMEM_GA>>>(
            xin, gin_W1 + (size_t)l*D*D, gin_b1 + l*D, T, NN,
            nullptr, slot, nullptr, nullptr, 0.f, 0, 0);
        // gemm2: direct-A BN+relu GEMM + relu -> XS[l]
        k_gemm<NT_NG,RPB_NG,0,1,1,0,1><<<GRID_NG, NT_NG, SMEM_WB>>>(
            T, gin_W2 + (size_t)l*D*D, gin_b2 + l*D, XS + (size_t)l*NN*D, NN,
            slot, nullptr, gin_g1 + l*D, gin_be1 + l*D, 1.0f / NN, 0, 0);
    }

    k_molptr<<<(NN + 255)/256, 256>>>(mol_ids);
    // JK: 3-pass accumulate -> X0
    k_gemm<NT_NG,RPB_NG,0,0,0,0,NL><<<GRID_NG, NT_NG, SMEM_WB>>>(
        XS, jk_W, jk_b, X0, NN,
        nullptr, nullptr, nullptr, nullptr, 0.f, (size_t)NN * D, (size_t)D * D);

    k_pool_seg<<<(NM*16 + 255)/256, 256>>>(X0);

    float* slot3 = stats + 3 * 2 * D;
    k_gemm<NT_NG,RPB_NG,0,0,0,1,1><<<(NM + RPB_NG - 1)/RPB_NG, NT_NG, SMEM_WB>>>(
        G, ffn_W1, ffn_b1, TG, NM,
        nullptr, slot3, nullptr, nullptr, 0.f, 0, 0);

    k_final<<<(NM + 255)/256, 256>>>(ffn_W2, out_W, ffn_b2, out_b,
                                     ffn_g, ffn_be, out, NM);
}